// round 12
// baseline (speedup 1.0000x reference)
#include <cuda_runtime.h>
#include <cstdint>
#include <math.h>

#define D_MODEL 768
#define D_FF    3072
#define N_EXP   9
#define N_TOK   2048
#define MAXROWS 4096

// ---------------- scratch (device globals: no allocation allowed) ----------
__device__ float g_h[MAXROWS * D_FF];          // hidden activations (gelu out)
__device__ float g_y[MAXROWS * D_MODEL];       // FFN outputs per row
__device__ float g_p[N_TOK];
__device__ int   g_e[N_TOK];
__device__ int   g_cnt[N_EXP];
__device__ int   g_pos[N_EXP];
__device__ int   g_base[N_EXP];
__device__ int   g_rowtok[MAXROWS];
__device__ int   g_rowidx[N_TOK];

// ---------------- PTX helpers (sm_80+, compute_103-safe) --------------------
__device__ __forceinline__ uint32_t smem_u32(const void* p) {
    uint32_t a;
    asm("{ .reg .u64 t; cvta.to.shared.u64 t, %1; cvt.u32.u64 %0, t; }"
        : "=r"(a) : "l"(p));
    return a;
}
#define CP_ASYNC16(dst_u32, src_ptr) \
    asm volatile("cp.async.cg.shared.global [%0], [%1], 16;" \
        :: "r"(dst_u32), "l"(src_ptr))
#define CP_COMMIT() asm volatile("cp.async.commit_group;")
#define CP_WAIT2()  asm volatile("cp.async.wait_group 2;")

__device__ __forceinline__ uint32_t to_tf32(float v) {
    uint32_t r;
    asm("cvt.rna.tf32.f32 %0, %1;" : "=r"(r) : "f"(v));
    return r;
}

__device__ __forceinline__ void ldmatrix_x4(uint32_t& r0, uint32_t& r1,
                                            uint32_t& r2, uint32_t& r3,
                                            uint32_t addr) {
    asm volatile("ldmatrix.sync.aligned.m8n8.x4.shared.b16 {%0,%1,%2,%3}, [%4];"
        : "=r"(r0), "=r"(r1), "=r"(r2), "=r"(r3) : "r"(addr));
}

__device__ __forceinline__ void mma_tf32(float* c, const uint32_t* a,
                                         const uint32_t* b) {
    asm volatile(
        "mma.sync.aligned.m16n8k8.row.col.f32.tf32.tf32.f32 "
        "{%0,%1,%2,%3}, {%4,%5,%6,%7}, {%8,%9}, {%0,%1,%2,%3};"
        : "+f"(c[0]), "+f"(c[1]), "+f"(c[2]), "+f"(c[3])
        : "r"(a[0]), "r"(a[1]), "r"(a[2]), "r"(a[3]),
          "r"(b[0]), "r"(b[1]));
}

// ---------------- tiny bookkeeping kernels ---------------------------------
__global__ void zero_kernel() {
    int i = threadIdx.x;
    if (i < N_EXP) { g_cnt[i] = 0; g_pos[i] = 0; }
}

__global__ void router_kernel(const float* __restrict__ x,
                              const float* __restrict__ Ws,
                              const float* __restrict__ bs) {
    int warp = (blockIdx.x * blockDim.x + threadIdx.x) >> 5;
    int lane = threadIdx.x & 31;
    if (warp >= N_TOK) return;
    const float* xr = x + (size_t)warp * D_MODEL;
    float acc[N_EXP];
#pragma unroll
    for (int e = 0; e < N_EXP; e++) acc[e] = 0.0f;
    for (int d = lane; d < D_MODEL; d += 32) {
        float xv = xr[d];
        const float* wr = Ws + d * N_EXP;
#pragma unroll
        for (int e = 0; e < N_EXP; e++) acc[e] += xv * wr[e];
    }
#pragma unroll
    for (int e = 0; e < N_EXP; e++) {
#pragma unroll
        for (int o = 16; o; o >>= 1)
            acc[e] += __shfl_xor_sync(0xffffffffu, acc[e], o);
    }
    if (lane == 0) {
        float l[N_EXP];
        float lmax = -1e30f; int am = 0;
#pragma unroll
        for (int e = 0; e < N_EXP; e++) {
            l[e] = acc[e] + bs[e];
            if (l[e] > lmax) { lmax = l[e]; am = e; }
        }
        float s = 0.0f;
#pragma unroll
        for (int e = 0; e < N_EXP; e++) s += expf(l[e] - lmax);
        g_p[warp] = 1.0f / s;
        g_e[warp] = am;
        atomicAdd(&g_cnt[am], 1);
    }
}

__global__ void scan_kernel() {
    int run = N_TOK;
    g_base[0] = 0;
    for (int e = 1; e < N_EXP; e++) { g_base[e] = run; run += g_cnt[e]; }
}

__global__ void assign_kernel() {
    int t = blockIdx.x * blockDim.x + threadIdx.x;
    if (t >= N_TOK) return;
    g_rowtok[t] = t;
    int e = g_e[t];
    if (e != 0) {
        int s = atomicAdd(&g_pos[e], 1);
        int row = g_base[e] + s;
        g_rowtok[row] = t;
        g_rowidx[t]   = row;
    }
}

// ---------------- mma.sync tf32 GEMM ----------------------------------------
// CTA tile 256(m) x 128(n) x 16(k). 256 threads = 8 warps, 4(m) x 2(n),
// warp tile 64x64. A smem [m][k] pitch 20 floats (ldmatrix-fed); B smem
// [k][n] pitch 136. 4-stage cp.async ring, one barrier per chunk.
#define KCHUNK 16
#define APITCH 20
#define BPITCH 136
#define ASZ (256 * APITCH)            // 5120 floats per stage
#define BSZ (KCHUNK * BPITCH)         // 2176 floats per stage
#define NSTAGE 4
#define SMEM_FLOATS (NSTAGE * (ASZ + BSZ))   // 29184 floats = 116736 B

template<int KDIM, int NTOT, bool GATHER, bool DO_GELU>
__global__ void __launch_bounds__(256)
gemm_mma(const float* __restrict__ A, const float* __restrict__ Bw,
         const float* __restrict__ bias, float* __restrict__ outp) {
    const int e    = blockIdx.z;
    const int rows = (e == 0) ? N_TOK : g_cnt[e];
    const int m0   = blockIdx.y * 256;
    if (m0 >= rows) return;
    const int base = (e == 0) ? 0 : g_base[e];
    const int n0   = blockIdx.x * 128;

    extern __shared__ float sm[];
    const uint32_t smb = smem_u32(sm);

    const int tid  = threadIdx.x;
    const int wid  = tid >> 5;
    const int lane = tid & 31;
    const int wm   = wid & 3;      // m-warp 0..3 (64 rows each)
    const int wn   = wid >> 2;     // n-warp 0..1 (64 cols each)
    const int qm   = lane >> 2;    // 0..7
    const int qk   = lane & 3;     // 0..3

    // ---- A cp.async: 256 rows x 16 floats = 1024 float4; 4 per thread ----
    const int arow_lo = tid >> 2;      // 0..63
    const int af4     = tid & 3;       // 0..3
    const float* asrc[4];
    uint32_t adst[4];
#pragma unroll
    for (int i = 0; i < 4; i++) {
        int r  = arow_lo + i * 64;          // 0..255 tile m row
        int m  = m0 + r;
        int mm = (m < rows) ? m : (rows - 1);
        const float* rowp;
        if (GATHER) rowp = A + (size_t)g_rowtok[base + mm] * KDIM;
        else        rowp = A + (size_t)(base + mm) * KDIM;
        asrc[i] = rowp + af4 * 4;
        adst[i] = (uint32_t)((r * APITCH + af4 * 4) * 4);
    }
    // ---- B cp.async: 16 k-rows x 128 floats = 512 float4; 2 per thread ----
    const int bk_lo = tid >> 5;        // 0..7
    const int bf4   = tid & 31;        // 0..31
    const float* Bbase = Bw + (size_t)e * KDIM * NTOT + n0 + bf4 * 4;
    uint32_t bdst[2];
#pragma unroll
    for (int i = 0; i < 2; i++) {
        int kk = bk_lo + i * 8;             // 0..15 tile k row
        bdst[i] = (uint32_t)((kk * BPITCH + bf4 * 4) * 4);
    }

    uint32_t abuf[NSTAGE], bbuf[NSTAGE];
    int aoff[NSTAGE], boff[NSTAGE];
#pragma unroll
    for (int s = 0; s < NSTAGE; s++) {
        aoff[s] = s * ASZ;
        boff[s] = NSTAGE * ASZ + s * BSZ;
        abuf[s] = smb + aoff[s] * 4;
        bbuf[s] = smb + boff[s] * 4;
    }

    // ldmatrix per-thread address part: sel = lane>>3 picks (row+8, k+4) combos
    const int sel = lane >> 3, r8 = lane & 7;
    const int a_lm_base =
        (wm * 64 + (sel & 1) * 8 + r8) * APITCH + (sel >> 1) * 4;

    auto load_chunk = [&](int buf, int k0) {
#pragma unroll
        for (int i = 0; i < 4; i++)
            CP_ASYNC16(abuf[buf] + adst[i], asrc[i] + k0);
#pragma unroll
        for (int i = 0; i < 2; i++)
            CP_ASYNC16(bbuf[buf] + bdst[i],
                       Bbase + (size_t)(k0 + bk_lo + i * 8) * NTOT);
        CP_COMMIT();
    };

    float acc[4][8][4];
#pragma unroll
    for (int tm = 0; tm < 4; tm++)
#pragma unroll
        for (int tn = 0; tn < 8; tn++)
#pragma unroll
            for (int j = 0; j < 4; j++) acc[tm][tn][j] = 0.0f;

    const int NC = KDIM / KCHUNK;
    load_chunk(0, 0);
    load_chunk(1, KCHUNK);

    for (int ch = 0; ch < NC; ch++) {
        const int buf = ch & (NSTAGE - 1);
        if (ch + 2 < NC) load_chunk((ch + 2) & (NSTAGE - 1), (ch + 2) * KCHUNK);
        else             CP_COMMIT();     // empty group keeps counting uniform
        CP_WAIT2();                        // chunk ch complete (own copies)
        __syncthreads();                   // publish to all warps

        const float* Bs = sm + boff[buf];
        const uint32_t a_lm0 = abuf[buf] + a_lm_base * 4;
#pragma unroll
        for (int k8 = 0; k8 < KCHUNK / 8; k8++) {
            const int kk0 = k8 * 8;
            uint32_t afr[4][4];
#pragma unroll
            for (int tm = 0; tm < 4; tm++) {
                ldmatrix_x4(afr[tm][0], afr[tm][1], afr[tm][2], afr[tm][3],
                            a_lm0 + (tm * 16 * APITCH + kk0) * 4);
#pragma unroll
                for (int j = 0; j < 4; j++)
                    afr[tm][j] = to_tf32(__uint_as_float(afr[tm][j]));
            }
            uint32_t bfr[8][2];
#pragma unroll
            for (int tn = 0; tn < 8; tn++) {
                const float* bp = Bs + (kk0 + qk) * BPITCH + wn * 64 + tn * 8 + qm;
                bfr[tn][0] = to_tf32(bp[0]);
                bfr[tn][1] = to_tf32(bp[4 * BPITCH]);
            }
#pragma unroll
            for (int tm = 0; tm < 4; tm++)
#pragma unroll
                for (int tn = 0; tn < 8; tn++)
                    mma_tf32(acc[tm][tn], afr[tm], bfr[tn]);
        }
        __syncthreads();                   // safe buffer reuse (distance 4)
    }

    // ---- epilogue: bias (+ gelu), direct global stores ----
    const float* bp_e = bias + (size_t)e * NTOT + n0 + wn * 64;
#pragma unroll
    for (int tm = 0; tm < 4; tm++) {
        int r0 = m0 + wm * 64 + tm * 16 + qm;
#pragma unroll
        for (int half = 0; half < 2; half++) {
            int r = r0 + half * 8;
            if (r >= rows) continue;
            float* orow = outp + (size_t)(base + r) * NTOT + n0 + wn * 64;
#pragma unroll
            for (int tn = 0; tn < 8; tn++) {
                int c = tn * 8 + qk * 2;
                float v0 = acc[tm][tn][half * 2 + 0] + __ldg(bp_e + c + 0);
                float v1 = acc[tm][tn][half * 2 + 1] + __ldg(bp_e + c + 1);
                if (DO_GELU) {
                    v0 = 0.5f * v0 * (1.0f + erff(v0 * 0.70710678118654752f));
                    v1 = 0.5f * v1 * (1.0f + erff(v1 * 0.70710678118654752f));
                }
                float2 o = make_float2(v0, v1);
                *(float2*)(orow + c) = o;
            }
        }
    }
}

// ---------------- combine ---------------------------------------------------
__global__ void combine_kernel(float* __restrict__ out) {
    int idx = blockIdx.x * blockDim.x + threadIdx.x;
    if (idx >= N_TOK * D_MODEL) return;
    int t = idx / D_MODEL;
    float y0 = g_y[idx];
    int e = g_e[t];
    float r;
    if (e == 0) {
        r = y0;
    } else {
        float p  = g_p[t];
        float ye = g_y[(size_t)g_rowidx[t] * D_MODEL + (idx - t * D_MODEL)];
        r = p * ye + (1.0f - p) * y0;
    }
    out[idx] = r;
}

// ---------------- launch ----------------------------------------------------
extern "C" void kernel_launch(void* const* d_in, const int* in_sizes, int n_in,
                              void* d_out, int out_size) {
    const float* x  = (const float*)d_in[0];
    const float* Ws = (const float*)d_in[1];
    const float* bs = (const float*)d_in[2];
    const float* W1 = (const float*)d_in[3];
    const float* b1 = (const float*)d_in[4];
    const float* W2 = (const float*)d_in[5];
    const float* b2 = (const float*)d_in[6];
    float* out = (float*)d_out;

    // CRITICAL: __device__ symbols must be resolved to DEVICE addresses here.
    float* hbuf; cudaGetSymbolAddress((void**)&hbuf, g_h);
    float* ybuf; cudaGetSymbolAddress((void**)&ybuf, g_y);

    const int smem_bytes = SMEM_FLOATS * 4;   // 116736
    cudaFuncSetAttribute((const void*)gemm_mma<D_MODEL, D_FF, true, true>,
                         cudaFuncAttributeMaxDynamicSharedMemorySize, smem_bytes);
    cudaFuncSetAttribute((const void*)gemm_mma<D_FF, D_MODEL, false, false>,
                         cudaFuncAttributeMaxDynamicSharedMemorySize, smem_bytes);

    zero_kernel<<<1, 32>>>();
    router_kernel<<<N_TOK / 8, 256>>>(x, Ws, bs);
    scan_kernel<<<1, 1>>>();
    assign_kernel<<<N_TOK / 256, 256>>>();

    // GEMM1: h = gelu(x @ W1 + b1); A gathered token rows, B = W1 [d][f]
    gemm_mma<D_MODEL, D_FF, true, true>
        <<<dim3(D_FF / 128, N_TOK / 256, N_EXP), 256, smem_bytes>>>(
            x, W1, b1, hbuf);
    // GEMM2: y = h @ W2 + b2; B = W2 [f][d]
    gemm_mma<D_FF, D_MODEL, false, false>
        <<<dim3(D_MODEL / 128, N_TOK / 256, N_EXP), 256, smem_bytes>>>(
            hbuf, W2, b2, ybuf);

    combine_kernel<<<(N_TOK * D_MODEL + 255) / 256, 256>>>(out);
}

// round 13
// speedup vs baseline: 1.2587x; 1.2587x over previous
#include <cuda_runtime.h>
#include <cstdint>
#include <math.h>

#define D_MODEL 768
#define D_FF    3072
#define N_EXP   9
#define N_TOK   2048
#define MAXROWS 4096

// ---------------- scratch (device globals: no allocation allowed) ----------
__device__ float g_h[MAXROWS * D_FF];          // hidden activations (gelu out)
__device__ float g_y[MAXROWS * D_MODEL];       // FFN outputs per row
__device__ float g_p[N_TOK];
__device__ int   g_e[N_TOK];
__device__ int   g_cnt[N_EXP];
__device__ int   g_pos[N_EXP];
__device__ int   g_base[N_EXP];
__device__ int   g_rowtok[MAXROWS];
__device__ int   g_rowidx[N_TOK];

// ---------------- PTX helpers (sm_80+, compute_103-safe) --------------------
__device__ __forceinline__ uint32_t smem_u32(const void* p) {
    uint32_t a;
    asm("{ .reg .u64 t; cvta.to.shared.u64 t, %1; cvt.u32.u64 %0, t; }"
        : "=r"(a) : "l"(p));
    return a;
}
#define CP_ASYNC16(dst_u32, src_ptr) \
    asm volatile("cp.async.cg.shared.global [%0], [%1], 16;" \
        :: "r"(dst_u32), "l"(src_ptr))
#define CP_COMMIT() asm volatile("cp.async.commit_group;")
#define CP_WAIT1()  asm volatile("cp.async.wait_group 1;")
#define CP_WAIT0()  asm volatile("cp.async.wait_group 0;")

// pack two f32 -> f16x2 register: lo = first arg, hi = second arg
__device__ __forceinline__ uint32_t pack_f16x2(float lo, float hi) {
    uint32_t r;
    asm("cvt.rn.f16x2.f32 %0, %1, %2;" : "=r"(r) : "f"(hi), "f"(lo));
    return r;
}

__device__ __forceinline__ void mma_f16(float* c, const uint32_t* a,
                                        const uint32_t* b) {
    asm volatile(
        "mma.sync.aligned.m16n8k16.row.col.f32.f16.f16.f32 "
        "{%0,%1,%2,%3}, {%4,%5,%6,%7}, {%8,%9}, {%0,%1,%2,%3};"
        : "+f"(c[0]), "+f"(c[1]), "+f"(c[2]), "+f"(c[3])
        : "r"(a[0]), "r"(a[1]), "r"(a[2]), "r"(a[3]),
          "r"(b[0]), "r"(b[1]));
}

// ---------------- tiny bookkeeping kernels ---------------------------------
__global__ void zero_kernel() {
    int i = threadIdx.x;
    if (i < N_EXP) { g_cnt[i] = 0; g_pos[i] = 0; }
}

__global__ void router_kernel(const float* __restrict__ x,
                              const float* __restrict__ Ws,
                              const float* __restrict__ bs) {
    int warp = (blockIdx.x * blockDim.x + threadIdx.x) >> 5;
    int lane = threadIdx.x & 31;
    if (warp >= N_TOK) return;
    const float* xr = x + (size_t)warp * D_MODEL;
    float acc[N_EXP];
#pragma unroll
    for (int e = 0; e < N_EXP; e++) acc[e] = 0.0f;
    for (int d = lane; d < D_MODEL; d += 32) {
        float xv = xr[d];
        const float* wr = Ws + d * N_EXP;
#pragma unroll
        for (int e = 0; e < N_EXP; e++) acc[e] += xv * wr[e];
    }
#pragma unroll
    for (int e = 0; e < N_EXP; e++) {
#pragma unroll
        for (int o = 16; o; o >>= 1)
            acc[e] += __shfl_xor_sync(0xffffffffu, acc[e], o);
    }
    if (lane == 0) {
        float l[N_EXP];
        float lmax = -1e30f; int am = 0;
#pragma unroll
        for (int e = 0; e < N_EXP; e++) {
            l[e] = acc[e] + bs[e];
            if (l[e] > lmax) { lmax = l[e]; am = e; }
        }
        float s = 0.0f;
#pragma unroll
        for (int e = 0; e < N_EXP; e++) s += expf(l[e] - lmax);
        g_p[warp] = 1.0f / s;
        g_e[warp] = am;
        atomicAdd(&g_cnt[am], 1);
    }
}

__global__ void scan_kernel() {
    int run = N_TOK;
    g_base[0] = 0;
    for (int e = 1; e < N_EXP; e++) { g_base[e] = run; run += g_cnt[e]; }
}

__global__ void assign_kernel() {
    int t = blockIdx.x * blockDim.x + threadIdx.x;
    if (t >= N_TOK) return;
    g_rowtok[t] = t;
    int e = g_e[t];
    if (e != 0) {
        int s = atomicAdd(&g_pos[e], 1);
        int row = g_base[e] + s;
        g_rowtok[row] = t;
        g_rowidx[t]   = row;
    }
}

// ---------------- mma.sync f16 GEMM (fp32 accumulate) -----------------------
// CTA tile 128(m) x 128(n) x 32(k). 256 threads = 8 warps, 4(m) x 2(n),
// warp tile 32x64, mma m16n8k16. A smem [m][k] fp32 pitch 36; B smem [k][n]
// fp32 pitch 132 (B fragment loads conflict-free: banks 8*qk+qm).
// fp32 -> f16x2 packing at fragment-load time. Double-buffered cp.async.
#define KCHUNK 32
#define APITCH 36
#define BPITCH 132
#define AFLOATS (128 * APITCH)        // 4608
#define BFLOATS (KCHUNK * BPITCH)     // 4224
#define SM_A0 0
#define SM_A1 AFLOATS
#define SM_B0 (2 * AFLOATS)
#define SM_B1 (2 * AFLOATS + BFLOATS)
#define SMEM_FLOATS (2 * AFLOATS + 2 * BFLOATS)   // 17664 floats = 70656 B

template<int KDIM, int NTOT, bool GATHER, bool DO_GELU>
__global__ void __launch_bounds__(256, 2)
gemm_mma(const float* __restrict__ A, const float* __restrict__ Bw,
         const float* __restrict__ bias, float* __restrict__ outp) {
    const int e    = blockIdx.z;
    const int rows = (e == 0) ? N_TOK : g_cnt[e];
    const int m0   = blockIdx.y * 128;
    if (m0 >= rows) return;
    const int base = (e == 0) ? 0 : g_base[e];
    const int n0   = blockIdx.x * 128;

    extern __shared__ float sm[];
    const uint32_t smb = smem_u32(sm);

    const int tid  = threadIdx.x;
    const int wid  = tid >> 5;
    const int lane = tid & 31;
    const int wm   = wid & 3;      // m-warp 0..3
    const int wn   = wid >> 2;     // n-warp 0..1
    const int qm   = lane >> 2;    // 0..7 (groupID)
    const int qk   = lane & 3;     // 0..3 (threadID in group)

    // ---- global source pointers (constant across chunks; add k offset) ----
    // A: 128 rows x 32 floats per chunk = 1024 float4; thread covers 4.
    const int arow_lo = tid >> 3;      // 0..31
    const int af4     = tid & 7;       // 0..7  (float4 within 32-float k chunk)
    const float* asrc[4];
    uint32_t adst[4];
#pragma unroll
    for (int i = 0; i < 4; i++) {
        int r  = arow_lo + i * 32;          // 0..127 tile m row
        int m  = m0 + r;
        int mm = (m < rows) ? m : (rows - 1);
        const float* rowp;
        if (GATHER) rowp = A + (size_t)g_rowtok[base + mm] * KDIM;
        else        rowp = A + (size_t)(base + mm) * KDIM;
        asrc[i] = rowp + af4 * 4;
        adst[i] = (uint32_t)((r * APITCH + af4 * 4) * 4);
    }
    // B: 32 k-rows x 128 floats per chunk = 1024 float4; thread covers 4.
    const int bk_lo = tid >> 5;        // 0..7
    const int bf4   = tid & 31;        // 0..31 (float4 within 128-float n row)
    const float* Bbase = Bw + (size_t)e * KDIM * NTOT + n0 + bf4 * 4;
    uint32_t bdst[4];
#pragma unroll
    for (int i = 0; i < 4; i++) {
        int kk = bk_lo + i * 8;             // 0..31 tile k row
        bdst[i] = (uint32_t)((kk * BPITCH + bf4 * 4) * 4);
    }

    const uint32_t abuf[2] = { smb + SM_A0 * 4, smb + SM_A1 * 4 };
    const uint32_t bbuf[2] = { smb + SM_B0 * 4, smb + SM_B1 * 4 };
    const int aoff[2] = { SM_A0, SM_A1 };
    const int boff[2] = { SM_B0, SM_B1 };

    auto load_chunk = [&](int buf, int k0) {
#pragma unroll
        for (int i = 0; i < 4; i++)
            CP_ASYNC16(abuf[buf] + adst[i], asrc[i] + k0);
#pragma unroll
        for (int i = 0; i < 4; i++)
            CP_ASYNC16(bbuf[buf] + bdst[i],
                       Bbase + (size_t)(k0 + bk_lo + i * 8) * NTOT);
        CP_COMMIT();
    };

    float acc[2][8][4];
#pragma unroll
    for (int tm = 0; tm < 2; tm++)
#pragma unroll
        for (int tn = 0; tn < 8; tn++)
#pragma unroll
            for (int j = 0; j < 4; j++) acc[tm][tn][j] = 0.0f;

    const int NC = KDIM / KCHUNK;
    load_chunk(0, 0);

    for (int ch = 0; ch < NC; ch++) {
        int buf = ch & 1;
        if (ch + 1 < NC) { load_chunk((ch + 1) & 1, (ch + 1) * KCHUNK); CP_WAIT1(); }
        else             { CP_WAIT0(); }
        __syncthreads();

        const float* As = sm + aoff[buf];
        const float* Bs = sm + boff[buf];
#pragma unroll
        for (int k16 = 0; k16 < KCHUNK / 16; k16++) {
            const int kk0 = k16 * 16;
            // ---- A fragments: m16n8k16 row-major ----
            // a0=(qm, 2qk,2qk+1) a1=(qm+8, ..) a2=(qm, +8 cols) a3=(qm+8, +8)
            uint32_t afr[2][4];
#pragma unroll
            for (int tm = 0; tm < 2; tm++) {
                const float* ap  = As + (wm * 32 + tm * 16 + qm) * APITCH + kk0 + 2 * qk;
                const float* ap8 = ap + 8 * APITCH;
                float2 v0  = *(const float2*)(ap);
                float2 v1  = *(const float2*)(ap8);
                float2 v2  = *(const float2*)(ap + 8);
                float2 v3  = *(const float2*)(ap8 + 8);
                afr[tm][0] = pack_f16x2(v0.x, v0.y);
                afr[tm][1] = pack_f16x2(v1.x, v1.y);
                afr[tm][2] = pack_f16x2(v2.x, v2.y);
                afr[tm][3] = pack_f16x2(v3.x, v3.y);
            }
            // ---- B fragments: b0=(2qk..2qk+1, n) b1=(+8 k, n) ----
            uint32_t bfr[8][2];
#pragma unroll
            for (int tn = 0; tn < 8; tn++) {
                const float* bp = Bs + (kk0 + 2 * qk) * BPITCH + wn * 64 + tn * 8 + qm;
                float f0 = bp[0];
                float f1 = bp[BPITCH];
                float f2 = bp[8 * BPITCH];
                float f3 = bp[9 * BPITCH];
                bfr[tn][0] = pack_f16x2(f0, f1);
                bfr[tn][1] = pack_f16x2(f2, f3);
            }
#pragma unroll
            for (int tm = 0; tm < 2; tm++)
#pragma unroll
                for (int tn = 0; tn < 8; tn++)
                    mma_f16(acc[tm][tn], afr[tm], bfr[tn]);
        }
        __syncthreads();
    }

    // ---- epilogue: bias (+ gelu), direct global stores ----
    const float* bp_e = bias + (size_t)e * NTOT + n0 + wn * 64;
#pragma unroll
    for (int tm = 0; tm < 2; tm++) {
        int r0 = m0 + wm * 32 + tm * 16 + qm;
#pragma unroll
        for (int half = 0; half < 2; half++) {
            int r = r0 + half * 8;
            if (r >= rows) continue;
            float* orow = outp + (size_t)(base + r) * NTOT + n0 + wn * 64;
#pragma unroll
            for (int tn = 0; tn < 8; tn++) {
                int c = tn * 8 + qk * 2;
                float v0 = acc[tm][tn][half * 2 + 0] + __ldg(bp_e + c + 0);
                float v1 = acc[tm][tn][half * 2 + 1] + __ldg(bp_e + c + 1);
                if (DO_GELU) {
                    v0 = 0.5f * v0 * (1.0f + erff(v0 * 0.70710678118654752f));
                    v1 = 0.5f * v1 * (1.0f + erff(v1 * 0.70710678118654752f));
                }
                float2 o = make_float2(v0, v1);
                *(float2*)(orow + c) = o;
            }
        }
    }
}

// ---------------- combine ---------------------------------------------------
__global__ void combine_kernel(float* __restrict__ out) {
    int idx = blockIdx.x * blockDim.x + threadIdx.x;
    if (idx >= N_TOK * D_MODEL) return;
    int t = idx / D_MODEL;
    float y0 = g_y[idx];
    int e = g_e[t];
    float r;
    if (e == 0) {
        r = y0;
    } else {
        float p  = g_p[t];
        float ye = g_y[(size_t)g_rowidx[t] * D_MODEL + (idx - t * D_MODEL)];
        r = p * ye + (1.0f - p) * y0;
    }
    out[idx] = r;
}

// ---------------- launch ----------------------------------------------------
extern "C" void kernel_launch(void* const* d_in, const int* in_sizes, int n_in,
                              void* d_out, int out_size) {
    const float* x  = (const float*)d_in[0];
    const float* Ws = (const float*)d_in[1];
    const float* bs = (const float*)d_in[2];
    const float* W1 = (const float*)d_in[3];
    const float* b1 = (const float*)d_in[4];
    const float* W2 = (const float*)d_in[5];
    const float* b2 = (const float*)d_in[6];
    float* out = (float*)d_out;

    // CRITICAL: __device__ symbols must be resolved to DEVICE addresses here.
    float* hbuf; cudaGetSymbolAddress((void**)&hbuf, g_h);
    float* ybuf; cudaGetSymbolAddress((void**)&ybuf, g_y);

    const int smem_bytes = SMEM_FLOATS * 4;   // 70656
    cudaFuncSetAttribute((const void*)gemm_mma<D_MODEL, D_FF, true, true>,
                         cudaFuncAttributeMaxDynamicSharedMemorySize, smem_bytes);
    cudaFuncSetAttribute((const void*)gemm_mma<D_FF, D_MODEL, false, false>,
                         cudaFuncAttributeMaxDynamicSharedMemorySize, smem_bytes);

    zero_kernel<<<1, 32>>>();
    router_kernel<<<N_TOK / 8, 256>>>(x, Ws, bs);
    scan_kernel<<<1, 1>>>();
    assign_kernel<<<N_TOK / 256, 256>>>();

    // GEMM1: h = gelu(x @ W1 + b1); A gathered token rows, B = W1 [d][f]
    gemm_mma<D_MODEL, D_FF, true, true>
        <<<dim3(D_FF / 128, N_TOK / 128, N_EXP), 256, smem_bytes>>>(
            x, W1, b1, hbuf);
    // GEMM2: y = h @ W2 + b2; B = W2 [f][d]
    gemm_mma<D_FF, D_MODEL, false, false>
        <<<dim3(D_MODEL / 128, N_TOK / 128, N_EXP), 256, smem_bytes>>>(
            hbuf, W2, b2, ybuf);

    combine_kernel<<<(N_TOK * D_MODEL + 255) / 256, 256>>>(out);
}

// round 14
// speedup vs baseline: 1.8148x; 1.4418x over previous
#include <cuda_runtime.h>
#include <cuda_fp16.h>
#include <cstdint>
#include <math.h>

#define D_MODEL 768
#define D_FF    3072
#define N_EXP   9
#define N_TOK   2048
#define MAXROWS 4096

// ---------------- scratch (device globals: no allocation allowed) ----------
__device__ __half g_xh[N_TOK * D_MODEL];          // x in fp16
__device__ __half g_w1h[N_EXP * D_MODEL * D_FF];  // W1 in fp16
__device__ __half g_w2h[N_EXP * D_FF * D_MODEL];  // W2 in fp16
__device__ __half g_hh[MAXROWS * D_FF];           // hidden activations fp16
__device__ float  g_y[MAXROWS * D_MODEL];         // FFN outputs fp32
__device__ float  g_p[N_TOK];
__device__ int    g_e[N_TOK];
__device__ int    g_cnt[N_EXP];
__device__ int    g_pos[N_EXP];
__device__ int    g_base[N_EXP];
__device__ int    g_rowtok[MAXROWS];
__device__ int    g_rowidx[N_TOK];

// ---------------- PTX helpers (sm_75+/80+, compute_103-safe) ---------------
__device__ __forceinline__ uint32_t smem_u32(const void* p) {
    uint32_t a;
    asm("{ .reg .u64 t; cvta.to.shared.u64 t, %1; cvt.u32.u64 %0, t; }"
        : "=r"(a) : "l"(p));
    return a;
}
#define CP_ASYNC16(dst_u32, src_ptr) \
    asm volatile("cp.async.cg.shared.global [%0], [%1], 16;" \
        :: "r"(dst_u32), "l"(src_ptr))
#define CP_COMMIT() asm volatile("cp.async.commit_group;")
#define CP_WAIT1()  asm volatile("cp.async.wait_group 1;")
#define CP_WAIT0()  asm volatile("cp.async.wait_group 0;")

__device__ __forceinline__ void ldsm_x4(uint32_t& r0, uint32_t& r1,
                                        uint32_t& r2, uint32_t& r3,
                                        uint32_t addr) {
    asm volatile("ldmatrix.sync.aligned.m8n8.x4.shared.b16 {%0,%1,%2,%3}, [%4];"
        : "=r"(r0), "=r"(r1), "=r"(r2), "=r"(r3) : "r"(addr));
}
__device__ __forceinline__ void ldsm_x4_t(uint32_t& r0, uint32_t& r1,
                                          uint32_t& r2, uint32_t& r3,
                                          uint32_t addr) {
    asm volatile("ldmatrix.sync.aligned.m8n8.x4.trans.shared.b16 {%0,%1,%2,%3}, [%4];"
        : "=r"(r0), "=r"(r1), "=r"(r2), "=r"(r3) : "r"(addr));
}

__device__ __forceinline__ void mma_f16(float* c, const uint32_t* a,
                                        const uint32_t* b) {
    asm volatile(
        "mma.sync.aligned.m16n8k16.row.col.f32.f16.f16.f32 "
        "{%0,%1,%2,%3}, {%4,%5,%6,%7}, {%8,%9}, {%0,%1,%2,%3};"
        : "+f"(c[0]), "+f"(c[1]), "+f"(c[2]), "+f"(c[3])
        : "r"(a[0]), "r"(a[1]), "r"(a[2]), "r"(a[3]),
          "r"(b[0]), "r"(b[1]));
}

// ---------------- fp32 -> fp16 conversion -----------------------------------
__global__ void f2h_kernel(const float* __restrict__ in,
                           __half* __restrict__ out, int n4) {
    int i = blockIdx.x * blockDim.x + threadIdx.x;
    if (i >= n4) return;
    float4 v = ((const float4*)in)[i];
    __half2* o = (__half2*)(out + (size_t)i * 4);
    o[0] = __floats2half2_rn(v.x, v.y);
    o[1] = __floats2half2_rn(v.z, v.w);
}

// ---------------- tiny bookkeeping kernels ---------------------------------
__global__ void zero_kernel() {
    int i = threadIdx.x;
    if (i < N_EXP) { g_cnt[i] = 0; g_pos[i] = 0; }
}

__global__ void router_kernel(const float* __restrict__ x,
                              const float* __restrict__ Ws,
                              const float* __restrict__ bs) {
    int warp = (blockIdx.x * blockDim.x + threadIdx.x) >> 5;
    int lane = threadIdx.x & 31;
    if (warp >= N_TOK) return;
    const float* xr = x + (size_t)warp * D_MODEL;
    float acc[N_EXP];
#pragma unroll
    for (int e = 0; e < N_EXP; e++) acc[e] = 0.0f;
    for (int d = lane; d < D_MODEL; d += 32) {
        float xv = xr[d];
        const float* wr = Ws + d * N_EXP;
#pragma unroll
        for (int e = 0; e < N_EXP; e++) acc[e] += xv * wr[e];
    }
#pragma unroll
    for (int e = 0; e < N_EXP; e++) {
#pragma unroll
        for (int o = 16; o; o >>= 1)
            acc[e] += __shfl_xor_sync(0xffffffffu, acc[e], o);
    }
    if (lane == 0) {
        float l[N_EXP];
        float lmax = -1e30f; int am = 0;
#pragma unroll
        for (int e = 0; e < N_EXP; e++) {
            l[e] = acc[e] + bs[e];
            if (l[e] > lmax) { lmax = l[e]; am = e; }
        }
        float s = 0.0f;
#pragma unroll
        for (int e = 0; e < N_EXP; e++) s += expf(l[e] - lmax);
        g_p[warp] = 1.0f / s;
        g_e[warp] = am;
        atomicAdd(&g_cnt[am], 1);
    }
}

__global__ void scan_kernel() {
    int run = N_TOK;
    g_base[0] = 0;
    for (int e = 1; e < N_EXP; e++) { g_base[e] = run; run += g_cnt[e]; }
}

__global__ void assign_kernel() {
    int t = blockIdx.x * blockDim.x + threadIdx.x;
    if (t >= N_TOK) return;
    g_rowtok[t] = t;
    int e = g_e[t];
    if (e != 0) {
        int s = atomicAdd(&g_pos[e], 1);
        int row = g_base[e] + s;
        g_rowtok[row] = t;
        g_rowidx[t]   = row;
    }
}

// ---------------- fp16 ldmatrix mma GEMM ------------------------------------
// CTA tile 128(m) x 128(n) x 32(k). 256 threads = 8 warps, 4(m) x 2(n),
// warp tile 32x64, mma m16n8k16. A smem [m][k] fp16 pitch 40 halves;
// B smem [k][n] fp16 pitch 136 halves. Both ldmatrix-fed, conflict-free.
// Double-buffered cp.async (fp16 payload). Static smem 37,888 B.
#define KCHUNK 32
#define APITCH_H 40
#define BPITCH_H 136
#define ASZ_H (128 * APITCH_H)        // 5120 halves / stage
#define BSZ_H (KCHUNK * BPITCH_H)     // 4352 halves / stage
#define SMEM_HALVES (2 * ASZ_H + 2 * BSZ_H)   // 18944 halves = 37888 B

template<int KDIM, int NTOT, bool GATHER, bool DO_GELU, typename OT>
__global__ void __launch_bounds__(256, 2)
gemm_mma(const __half* __restrict__ A, const __half* __restrict__ Bw,
         const float* __restrict__ bias, OT* __restrict__ outp) {
    const int e    = blockIdx.z;
    const int rows = (e == 0) ? N_TOK : g_cnt[e];
    const int m0   = blockIdx.y * 128;
    if (m0 >= rows) return;
    const int base = (e == 0) ? 0 : g_base[e];
    const int n0   = blockIdx.x * 128;

    __shared__ __half sm[SMEM_HALVES];
    const uint32_t smb = smem_u32(sm);

    const int tid  = threadIdx.x;
    const int wid  = tid >> 5;
    const int lane = tid & 31;
    const int wm   = wid & 3;      // m-warp 0..3
    const int wn   = wid >> 2;     // n-warp 0..1
    const int qm   = lane >> 2;    // 0..7
    const int qk   = lane & 3;     // 0..3

    // ---- A cp.async: 128 rows x 32 halves (64B) = 512 x 16B; 2/thread ----
    const int ar = tid >> 2;           // 0..63
    const int ac = tid & 3;            // 0..3 (16B unit in 64B row chunk)
    const __half* asrc[2];
    uint32_t adst[2];
#pragma unroll
    for (int i = 0; i < 2; i++) {
        int r  = ar + i * 64;               // 0..127 tile m row
        int m  = m0 + r;
        int mm = (m < rows) ? m : (rows - 1);
        const __half* rowp;
        if (GATHER) rowp = A + (size_t)g_rowtok[base + mm] * KDIM;
        else        rowp = A + (size_t)(base + mm) * KDIM;
        asrc[i] = rowp + ac * 8;
        adst[i] = (uint32_t)((r * APITCH_H + ac * 8) * 2);
    }
    // ---- B cp.async: 32 k-rows x 128 halves (256B) = 512 x 16B; 2/thread --
    const int bk = tid >> 4;           // 0..15
    const int bc = tid & 15;           // 0..15 (16B unit in 256B row)
    const __half* Bbase = Bw + (size_t)e * KDIM * NTOT + n0 + bc * 8;
    uint32_t bdst[2];
#pragma unroll
    for (int i = 0; i < 2; i++) {
        int kk = bk + i * 16;               // 0..31 tile k row
        bdst[i] = (uint32_t)((kk * BPITCH_H + bc * 8) * 2);
    }

    const uint32_t abuf[2] = { smb, smb + ASZ_H * 2 };
    const uint32_t bbuf[2] = { smb + 2 * ASZ_H * 2,
                               smb + (2 * ASZ_H + BSZ_H) * 2 };

    auto load_chunk = [&](int buf, int k0) {
#pragma unroll
        for (int i = 0; i < 2; i++)
            CP_ASYNC16(abuf[buf] + adst[i], asrc[i] + k0);
#pragma unroll
        for (int i = 0; i < 2; i++)
            CP_ASYNC16(bbuf[buf] + bdst[i],
                       Bbase + (size_t)(k0 + bk + i * 16) * NTOT);
        CP_COMMIT();
    };

    // ---- ldmatrix per-lane address components ----
    // A x4: m = lane&15 (within warp 16-row block), k-block = lane>>4
    const uint32_t a_lm =
        (uint32_t)(((wm * 32 + (lane & 15)) * APITCH_H + (lane >> 4) * 8) * 2);
    // B x4 trans: k-row = lane&15, n 8-block = lane>>4
    const uint32_t b_lm =
        (uint32_t)(((lane & 15) * BPITCH_H + wn * 64 + (lane >> 4) * 8) * 2);

    float acc[2][8][4];
#pragma unroll
    for (int tm = 0; tm < 2; tm++)
#pragma unroll
        for (int tn = 0; tn < 8; tn++)
#pragma unroll
            for (int j = 0; j < 4; j++) acc[tm][tn][j] = 0.0f;

    const int NC = KDIM / KCHUNK;
    load_chunk(0, 0);

    for (int ch = 0; ch < NC; ch++) {
        int buf = ch & 1;
        if (ch + 1 < NC) { load_chunk((ch + 1) & 1, (ch + 1) * KCHUNK); CP_WAIT1(); }
        else             { CP_WAIT0(); }
        __syncthreads();

        const uint32_t a0 = abuf[buf] + a_lm;
        const uint32_t b0 = bbuf[buf] + b_lm;
#pragma unroll
        for (int k16 = 0; k16 < KCHUNK / 16; k16++) {
            uint32_t afr[2][4];
#pragma unroll
            for (int tm = 0; tm < 2; tm++)
                ldsm_x4(afr[tm][0], afr[tm][1], afr[tm][2], afr[tm][3],
                        a0 + (uint32_t)((tm * 16 * APITCH_H + k16 * 16) * 2));
            uint32_t bfr[8][2];
#pragma unroll
            for (int j = 0; j < 4; j++) {
                uint32_t r0, r1, r2, r3;
                ldsm_x4_t(r0, r1, r2, r3,
                          b0 + (uint32_t)((k16 * 16 * BPITCH_H + j * 16) * 2));
                bfr[2 * j + 0][0] = r0; bfr[2 * j + 0][1] = r1;
                bfr[2 * j + 1][0] = r2; bfr[2 * j + 1][1] = r3;
            }
#pragma unroll
            for (int tm = 0; tm < 2; tm++)
#pragma unroll
                for (int tn = 0; tn < 8; tn++)
                    mma_f16(acc[tm][tn], afr[tm], bfr[tn]);
        }
        __syncthreads();
    }

    // ---- epilogue: bias (+ gelu), direct global stores ----
    const float* bp_e = bias + (size_t)e * NTOT + n0 + wn * 64;
#pragma unroll
    for (int tm = 0; tm < 2; tm++) {
        int r0 = m0 + wm * 32 + tm * 16 + qm;
#pragma unroll
        for (int half = 0; half < 2; half++) {
            int r = r0 + half * 8;
            if (r >= rows) continue;
            OT* orow = outp + (size_t)(base + r) * NTOT + n0 + wn * 64;
#pragma unroll
            for (int tn = 0; tn < 8; tn++) {
                int c = tn * 8 + qk * 2;
                float v0 = acc[tm][tn][half * 2 + 0] + __ldg(bp_e + c + 0);
                float v1 = acc[tm][tn][half * 2 + 1] + __ldg(bp_e + c + 1);
                if (DO_GELU) {
                    v0 = 0.5f * v0 * (1.0f + erff(v0 * 0.70710678118654752f));
                    v1 = 0.5f * v1 * (1.0f + erff(v1 * 0.70710678118654752f));
                }
                if (sizeof(OT) == 2) {
                    *(__half2*)((__half*)orow + c) = __floats2half2_rn(v0, v1);
                } else {
                    *(float2*)((float*)orow + c) = make_float2(v0, v1);
                }
            }
        }
    }
}

// ---------------- combine ---------------------------------------------------
__global__ void combine_kernel(float* __restrict__ out) {
    int idx = blockIdx.x * blockDim.x + threadIdx.x;
    if (idx >= N_TOK * D_MODEL) return;
    int t = idx / D_MODEL;
    float y0 = g_y[idx];
    int e = g_e[t];
    float r;
    if (e == 0) {
        r = y0;
    } else {
        float p  = g_p[t];
        float ye = g_y[(size_t)g_rowidx[t] * D_MODEL + (idx - t * D_MODEL)];
        r = p * ye + (1.0f - p) * y0;
    }
    out[idx] = r;
}

// ---------------- launch ----------------------------------------------------
extern "C" void kernel_launch(void* const* d_in, const int* in_sizes, int n_in,
                              void* d_out, int out_size) {
    const float* x  = (const float*)d_in[0];
    const float* Ws = (const float*)d_in[1];
    const float* bs = (const float*)d_in[2];
    const float* W1 = (const float*)d_in[3];
    const float* b1 = (const float*)d_in[4];
    const float* W2 = (const float*)d_in[5];
    const float* b2 = (const float*)d_in[6];
    float* out = (float*)d_out;

    // CRITICAL: __device__ symbols must be resolved to DEVICE addresses here.
    __half* xh;  cudaGetSymbolAddress((void**)&xh,  g_xh);
    __half* w1h; cudaGetSymbolAddress((void**)&w1h, g_w1h);
    __half* w2h; cudaGetSymbolAddress((void**)&w2h, g_w2h);
    __half* hh;  cudaGetSymbolAddress((void**)&hh,  g_hh);
    float*  ybuf; cudaGetSymbolAddress((void**)&ybuf, g_y);

    zero_kernel<<<1, 32>>>();
    router_kernel<<<N_TOK / 8, 256>>>(x, Ws, bs);
    scan_kernel<<<1, 1>>>();
    assign_kernel<<<N_TOK / 256, 256>>>();

    // fp32 -> fp16 conversions
    {
        int n4;
        n4 = N_TOK * D_MODEL / 4;
        f2h_kernel<<<(n4 + 255) / 256, 256>>>(x, xh, n4);
        n4 = N_EXP * D_MODEL * D_FF / 4;
        f2h_kernel<<<(n4 + 255) / 256, 256>>>(W1, w1h, n4);
        n4 = N_EXP * D_FF * D_MODEL / 4;
        f2h_kernel<<<(n4 + 255) / 256, 256>>>(W2, w2h, n4);
    }

    // GEMM1: h = gelu(x @ W1 + b1); gathered fp16 x rows, fp16 W1, fp16 out
    gemm_mma<D_MODEL, D_FF, true, true, __half>
        <<<dim3(D_FF / 128, N_TOK / 128, N_EXP), 256>>>(
            xh, w1h, b1, hh);
    // GEMM2: y = h @ W2 + b2; fp16 h, fp16 W2, fp32 out
    gemm_mma<D_FF, D_MODEL, false, false, float>
        <<<dim3(D_MODEL / 128, N_TOK / 128, N_EXP), 256>>>(
            hh, w2h, b2, ybuf);

    combine_kernel<<<(N_TOK * D_MODEL + 255) / 256, 256>>>(out);
}

// round 15
// speedup vs baseline: 1.9953x; 1.0994x over previous
#include <cuda_runtime.h>
#include <cuda_fp16.h>
#include <cstdint>
#include <math.h>

#define D_MODEL 768
#define D_FF    3072
#define N_EXP   9
#define N_TOK   2048
#define MAXROWS 4096

// ---------------- scratch (device globals: no allocation allowed) ----------
__device__ __half g_xh[N_TOK * D_MODEL];          // x in fp16
__device__ __half g_w1h[N_EXP * D_MODEL * D_FF];  // W1 in fp16
__device__ __half g_w2h[N_EXP * D_FF * D_MODEL];  // W2 in fp16
__device__ __half g_hh[MAXROWS * D_FF];           // hidden activations fp16
__device__ float  g_y[MAXROWS * D_MODEL];         // FFN partial (K first half + bias)
__device__ float  g_y2[MAXROWS * D_MODEL];        // FFN partial (K second half)
__device__ float  g_p[N_TOK];
__device__ int    g_e[N_TOK];
__device__ int    g_cnt[N_EXP];
__device__ int    g_pos[N_EXP];
__device__ int    g_base[N_EXP];
__device__ int    g_rowtok[MAXROWS];
__device__ int    g_rowidx[N_TOK];

// ---------------- PTX helpers (sm_75+/80+, compute_103-safe) ---------------
__device__ __forceinline__ uint32_t smem_u32(const void* p) {
    uint32_t a;
    asm("{ .reg .u64 t; cvta.to.shared.u64 t, %1; cvt.u32.u64 %0, t; }"
        : "=r"(a) : "l"(p));
    return a;
}
#define CP_ASYNC16(dst_u32, src_ptr) \
    asm volatile("cp.async.cg.shared.global [%0], [%1], 16;" \
        :: "r"(dst_u32), "l"(src_ptr))
#define CP_COMMIT() asm volatile("cp.async.commit_group;")
#define CP_WAIT1()  asm volatile("cp.async.wait_group 1;")
#define CP_WAIT0()  asm volatile("cp.async.wait_group 0;")

__device__ __forceinline__ void ldsm_x4(uint32_t& r0, uint32_t& r1,
                                        uint32_t& r2, uint32_t& r3,
                                        uint32_t addr) {
    asm volatile("ldmatrix.sync.aligned.m8n8.x4.shared.b16 {%0,%1,%2,%3}, [%4];"
        : "=r"(r0), "=r"(r1), "=r"(r2), "=r"(r3) : "r"(addr));
}
__device__ __forceinline__ void ldsm_x4_t(uint32_t& r0, uint32_t& r1,
                                          uint32_t& r2, uint32_t& r3,
                                          uint32_t addr) {
    asm volatile("ldmatrix.sync.aligned.m8n8.x4.trans.shared.b16 {%0,%1,%2,%3}, [%4];"
        : "=r"(r0), "=r"(r1), "=r"(r2), "=r"(r3) : "r"(addr));
}

__device__ __forceinline__ void mma_f16(float* c, const uint32_t* a,
                                        const uint32_t* b) {
    asm volatile(
        "mma.sync.aligned.m16n8k16.row.col.f32.f16.f16.f32 "
        "{%0,%1,%2,%3}, {%4,%5,%6,%7}, {%8,%9}, {%0,%1,%2,%3};"
        : "+f"(c[0]), "+f"(c[1]), "+f"(c[2]), "+f"(c[3])
        : "r"(a[0]), "r"(a[1]), "r"(a[2]), "r"(a[3]),
          "r"(b[0]), "r"(b[1]));
}

// ---------------- fp32 -> fp16 conversion (both weights, one launch) --------
__global__ void w2h_kernel(const float* __restrict__ w1,
                           const float* __restrict__ w2,
                           __half* __restrict__ o1,
                           __half* __restrict__ o2, int n4) {
    int i = blockIdx.x * blockDim.x + threadIdx.x;
    if (i >= n4) return;
    const float* in = blockIdx.y ? w2 : w1;
    __half* out = blockIdx.y ? o2 : o1;
    float4 v = ((const float4*)in)[i];
    __half2* o = (__half2*)(out + (size_t)i * 4);
    o[0] = __floats2half2_rn(v.x, v.y);
    o[1] = __floats2half2_rn(v.z, v.w);
}

// ---------------- tiny bookkeeping kernels ---------------------------------
__global__ void zero_kernel() {
    int i = threadIdx.x;
    if (i < N_EXP) { g_cnt[i] = 0; g_pos[i] = 0; }
}

// router + fused x -> fp16 conversion
__global__ void router_kernel(const float* __restrict__ x,
                              const float* __restrict__ Ws,
                              const float* __restrict__ bs) {
    int warp = (blockIdx.x * blockDim.x + threadIdx.x) >> 5;
    int lane = threadIdx.x & 31;
    if (warp >= N_TOK) return;
    const float* xr = x + (size_t)warp * D_MODEL;
    __half* xo = g_xh + (size_t)warp * D_MODEL;
    float acc[N_EXP];
#pragma unroll
    for (int e = 0; e < N_EXP; e++) acc[e] = 0.0f;
    for (int d = lane; d < D_MODEL; d += 32) {
        float xv = xr[d];
        xo[d] = __float2half_rn(xv);
        const float* wr = Ws + d * N_EXP;
#pragma unroll
        for (int e = 0; e < N_EXP; e++) acc[e] += xv * wr[e];
    }
#pragma unroll
    for (int e = 0; e < N_EXP; e++) {
#pragma unroll
        for (int o = 16; o; o >>= 1)
            acc[e] += __shfl_xor_sync(0xffffffffu, acc[e], o);
    }
    if (lane == 0) {
        float l[N_EXP];
        float lmax = -1e30f; int am = 0;
#pragma unroll
        for (int e = 0; e < N_EXP; e++) {
            l[e] = acc[e] + bs[e];
            if (l[e] > lmax) { lmax = l[e]; am = e; }
        }
        float s = 0.0f;
#pragma unroll
        for (int e = 0; e < N_EXP; e++) s += expf(l[e] - lmax);
        g_p[warp] = 1.0f / s;
        g_e[warp] = am;
        atomicAdd(&g_cnt[am], 1);
    }
}

__global__ void scan_kernel() {
    int run = N_TOK;
    g_base[0] = 0;
    for (int e = 1; e < N_EXP; e++) { g_base[e] = run; run += g_cnt[e]; }
}

__global__ void assign_kernel() {
    int t = blockIdx.x * blockDim.x + threadIdx.x;
    if (t >= N_TOK) return;
    g_rowtok[t] = t;
    int e = g_e[t];
    if (e != 0) {
        int s = atomicAdd(&g_pos[e], 1);
        int row = g_base[e] + s;
        g_rowtok[row] = t;
        g_rowidx[t]   = row;
    }
}

// ---------------- fp16 ldmatrix mma GEMM ------------------------------------
// CTA tile 128(m) x 128(n) x 32(k). 256 threads = 8 warps, 4(m) x 2(n),
// warp tile 32x64, mma m16n8k16. A smem [m][k] fp16 pitch 40 halves;
// B smem [k][n] fp16 pitch 136 halves. Both ldmatrix-fed, conflict-free.
// Double-buffered cp.async (fp16 payload). Static smem 37,888 B.
// SPLITK: blockIdx.z = e*2+sk; sk selects K half + output buffer; bias on sk=0.
#define KCHUNK 32
#define APITCH_H 40
#define BPITCH_H 136
#define ASZ_H (128 * APITCH_H)        // 5120 halves / stage
#define BSZ_H (KCHUNK * BPITCH_H)     // 4352 halves / stage
#define SMEM_HALVES (2 * ASZ_H + 2 * BSZ_H)   // 18944 halves = 37888 B

template<int KSTRIDE, int KDIM, int NTOT, bool GATHER, bool DO_GELU,
         bool SPLITK, typename OT>
__global__ void __launch_bounds__(256, 2)
gemm_mma(const __half* __restrict__ A, const __half* __restrict__ Bw,
         const float* __restrict__ bias, OT* __restrict__ outp,
         OT* __restrict__ outp2) {
    int e, sk;
    if (SPLITK) { e = blockIdx.z >> 1; sk = blockIdx.z & 1; }
    else        { e = blockIdx.z;      sk = 0; }
    const int rows = (e == 0) ? N_TOK : g_cnt[e];
    const int m0   = blockIdx.y * 128;
    if (m0 >= rows) return;
    const int base = (e == 0) ? 0 : g_base[e];
    const int n0   = blockIdx.x * 128;
    const int koff = sk * KDIM;
    OT* optr = (SPLITK && sk) ? outp2 : outp;

    __shared__ __half sm[SMEM_HALVES];
    const uint32_t smb = smem_u32(sm);

    const int tid  = threadIdx.x;
    const int wid  = tid >> 5;
    const int lane = tid & 31;
    const int wm   = wid & 3;      // m-warp 0..3
    const int wn   = wid >> 2;     // n-warp 0..1
    const int qm   = lane >> 2;    // 0..7
    const int qk   = lane & 3;     // 0..3

    // ---- A cp.async: 128 rows x 32 halves (64B) = 512 x 16B; 2/thread ----
    const int ar = tid >> 2;           // 0..63
    const int ac = tid & 3;            // 0..3 (16B unit in 64B row chunk)
    const __half* asrc[2];
    uint32_t adst[2];
#pragma unroll
    for (int i = 0; i < 2; i++) {
        int r  = ar + i * 64;               // 0..127 tile m row
        int m  = m0 + r;
        int mm = (m < rows) ? m : (rows - 1);
        const __half* rowp;
        if (GATHER) rowp = A + (size_t)g_rowtok[base + mm] * KSTRIDE;
        else        rowp = A + (size_t)(base + mm) * KSTRIDE;
        asrc[i] = rowp + koff + ac * 8;
        adst[i] = (uint32_t)((r * APITCH_H + ac * 8) * 2);
    }
    // ---- B cp.async: 32 k-rows x 128 halves (256B) = 512 x 16B; 2/thread --
    const int bk = tid >> 4;           // 0..15
    const int bc = tid & 15;           // 0..15 (16B unit in 256B row)
    const __half* Bbase =
        Bw + (size_t)e * KSTRIDE * NTOT + (size_t)koff * NTOT + n0 + bc * 8;
    uint32_t bdst[2];
#pragma unroll
    for (int i = 0; i < 2; i++) {
        int kk = bk + i * 16;               // 0..31 tile k row
        bdst[i] = (uint32_t)((kk * BPITCH_H + bc * 8) * 2);
    }

    const uint32_t abuf[2] = { smb, smb + ASZ_H * 2 };
    const uint32_t bbuf[2] = { smb + 2 * ASZ_H * 2,
                               smb + (2 * ASZ_H + BSZ_H) * 2 };

    auto load_chunk = [&](int buf, int k0) {
#pragma unroll
        for (int i = 0; i < 2; i++)
            CP_ASYNC16(abuf[buf] + adst[i], asrc[i] + k0);
#pragma unroll
        for (int i = 0; i < 2; i++)
            CP_ASYNC16(bbuf[buf] + bdst[i],
                       Bbase + (size_t)(k0 + bk + i * 16) * NTOT);
        CP_COMMIT();
    };

    // ---- ldmatrix per-lane address components ----
    const uint32_t a_lm =
        (uint32_t)(((wm * 32 + (lane & 15)) * APITCH_H + (lane >> 4) * 8) * 2);
    const uint32_t b_lm =
        (uint32_t)(((lane & 15) * BPITCH_H + wn * 64 + (lane >> 4) * 8) * 2);

    float acc[2][8][4];
#pragma unroll
    for (int tm = 0; tm < 2; tm++)
#pragma unroll
        for (int tn = 0; tn < 8; tn++)
#pragma unroll
            for (int j = 0; j < 4; j++) acc[tm][tn][j] = 0.0f;

    const int NC = KDIM / KCHUNK;
    load_chunk(0, 0);

    for (int ch = 0; ch < NC; ch++) {
        int buf = ch & 1;
        if (ch + 1 < NC) { load_chunk((ch + 1) & 1, (ch + 1) * KCHUNK); CP_WAIT1(); }
        else             { CP_WAIT0(); }
        __syncthreads();

        const uint32_t a0 = abuf[buf] + a_lm;
        const uint32_t b0 = bbuf[buf] + b_lm;
#pragma unroll
        for (int k16 = 0; k16 < KCHUNK / 16; k16++) {
            uint32_t afr[2][4];
#pragma unroll
            for (int tm = 0; tm < 2; tm++)
                ldsm_x4(afr[tm][0], afr[tm][1], afr[tm][2], afr[tm][3],
                        a0 + (uint32_t)((tm * 16 * APITCH_H + k16 * 16) * 2));
            uint32_t bfr[8][2];
#pragma unroll
            for (int j = 0; j < 4; j++) {
                uint32_t r0, r1, r2, r3;
                ldsm_x4_t(r0, r1, r2, r3,
                          b0 + (uint32_t)((k16 * 16 * BPITCH_H + j * 16) * 2));
                bfr[2 * j + 0][0] = r0; bfr[2 * j + 0][1] = r1;
                bfr[2 * j + 1][0] = r2; bfr[2 * j + 1][1] = r3;
            }
#pragma unroll
            for (int tm = 0; tm < 2; tm++)
#pragma unroll
                for (int tn = 0; tn < 8; tn++)
                    mma_f16(acc[tm][tn], afr[tm], bfr[tn]);
        }
        __syncthreads();
    }

    // ---- epilogue: bias (+ gelu) on sk==0 only; direct global stores ----
    const bool add_bias = (!SPLITK) || (sk == 0);
    const float* bp_e = bias + (size_t)e * NTOT + n0 + wn * 64;
#pragma unroll
    for (int tm = 0; tm < 2; tm++) {
        int r0 = m0 + wm * 32 + tm * 16 + qm;
#pragma unroll
        for (int half = 0; half < 2; half++) {
            int r = r0 + half * 8;
            if (r >= rows) continue;
            OT* orow = optr + (size_t)(base + r) * NTOT + n0 + wn * 64;
#pragma unroll
            for (int tn = 0; tn < 8; tn++) {
                int c = tn * 8 + qk * 2;
                float v0 = acc[tm][tn][half * 2 + 0];
                float v1 = acc[tm][tn][half * 2 + 1];
                if (add_bias) {
                    v0 += __ldg(bp_e + c + 0);
                    v1 += __ldg(bp_e + c + 1);
                }
                if (DO_GELU) {
                    v0 = 0.5f * v0 * (1.0f + erff(v0 * 0.70710678118654752f));
                    v1 = 0.5f * v1 * (1.0f + erff(v1 * 0.70710678118654752f));
                }
                if (sizeof(OT) == 2) {
                    *(__half2*)((__half*)orow + c) = __floats2half2_rn(v0, v1);
                } else {
                    *(float2*)((float*)orow + c) = make_float2(v0, v1);
                }
            }
        }
    }
}

// ---------------- combine (sums split-K partials) ----------------------------
__global__ void combine_kernel(float* __restrict__ out) {
    int idx = blockIdx.x * blockDim.x + threadIdx.x;
    if (idx >= N_TOK * D_MODEL) return;
    int t = idx / D_MODEL;
    float y0 = g_y[idx] + g_y2[idx];
    int e = g_e[t];
    float r;
    if (e == 0) {
        r = y0;
    } else {
        float p  = g_p[t];
        size_t ri = (size_t)g_rowidx[t] * D_MODEL + (idx - t * D_MODEL);
        float ye = g_y[ri] + g_y2[ri];
        r = p * ye + (1.0f - p) * y0;
    }
    out[idx] = r;
}

// ---------------- launch ----------------------------------------------------
extern "C" void kernel_launch(void* const* d_in, const int* in_sizes, int n_in,
                              void* d_out, int out_size) {
    const float* x  = (const float*)d_in[0];
    const float* Ws = (const float*)d_in[1];
    const float* bs = (const float*)d_in[2];
    const float* W1 = (const float*)d_in[3];
    const float* b1 = (const float*)d_in[4];
    const float* W2 = (const float*)d_in[5];
    const float* b2 = (const float*)d_in[6];
    float* out = (float*)d_out;

    // CRITICAL: __device__ symbols must be resolved to DEVICE addresses here.
    __half* xh;  cudaGetSymbolAddress((void**)&xh,  g_xh);
    __half* w1h; cudaGetSymbolAddress((void**)&w1h, g_w1h);
    __half* w2h; cudaGetSymbolAddress((void**)&w2h, g_w2h);
    __half* hh;  cudaGetSymbolAddress((void**)&hh,  g_hh);
    float*  ybuf;  cudaGetSymbolAddress((void**)&ybuf,  g_y);
    float*  ybuf2; cudaGetSymbolAddress((void**)&ybuf2, g_y2);

    zero_kernel<<<1, 32>>>();
    router_kernel<<<N_TOK / 8, 256>>>(x, Ws, bs);   // also writes g_xh
    scan_kernel<<<1, 1>>>();
    assign_kernel<<<N_TOK / 256, 256>>>();

    // fp32 -> fp16 weight conversions (one launch; W1 and W2 same size)
    {
        int n4 = N_EXP * D_MODEL * D_FF / 4;
        w2h_kernel<<<dim3((n4 + 255) / 256, 2), 256>>>(W1, W2, w1h, w2h, n4);
    }

    // GEMM1: h = gelu(x @ W1 + b1); gathered fp16 x rows, fp16 W1, fp16 out
    gemm_mma<D_MODEL, D_MODEL, D_FF, true, true, false, __half>
        <<<dim3(D_FF / 128, N_TOK / 128, N_EXP), 256>>>(
            xh, w1h, b1, hh, hh);
    // GEMM2: y = h @ W2 + b2; split-K=2 -> partials in g_y / g_y2
    gemm_mma<D_FF, D_FF / 2, D_MODEL, false, false, true, float>
        <<<dim3(D_MODEL / 128, N_TOK / 128, N_EXP * 2), 256>>>(
            hh, w2h, b2, ybuf, ybuf2);

    combine_kernel<<<(N_TOK * D_MODEL + 255) / 256, 256>>>(out);
}

// round 16
// speedup vs baseline: 2.0529x; 1.0289x over previous
#include <cuda_runtime.h>
#include <cuda_fp16.h>
#include <cstdint>
#include <math.h>

#define D_MODEL 768
#define D_FF    3072
#define N_EXP   9
#define N_TOK   2048
#define SEG     2048                  // fixed rows per expert segment
#define MAXR    (SEG * N_EXP)         // 18432 rows

// ---------------- scratch (device globals: no allocation allowed) ----------
__device__ __half g_xh[N_TOK * D_MODEL];          // x in fp16
__device__ __half g_w1h[N_EXP * D_MODEL * D_FF];  // W1 in fp16
__device__ __half g_w2h[N_EXP * D_FF * D_MODEL];  // W2 in fp16
__device__ __half g_hh[(size_t)MAXR * D_FF];      // hidden activations fp16
__device__ float  g_y[(size_t)MAXR * D_MODEL];    // split-K partial 0 (+bias)
__device__ float  g_y2[(size_t)MAXR * D_MODEL];   // split-K partial 1
__device__ float  g_y3[(size_t)MAXR * D_MODEL];   // split-K partial 2
__device__ float  g_y4[(size_t)MAXR * D_MODEL];   // split-K partial 3
__device__ float  g_p[N_TOK];
__device__ int    g_e[N_TOK];
__device__ int    g_cnt[N_EXP];
__device__ int    g_pos[N_EXP];
__device__ int    g_rowtok[MAXR];
__device__ int    g_rowidx[N_TOK];

// ---------------- PTX helpers (sm_75+/80+, compute_103-safe) ---------------
__device__ __forceinline__ uint32_t smem_u32(const void* p) {
    uint32_t a;
    asm("{ .reg .u64 t; cvta.to.shared.u64 t, %1; cvt.u32.u64 %0, t; }"
        : "=r"(a) : "l"(p));
    return a;
}
#define CP_ASYNC16(dst_u32, src_ptr) \
    asm volatile("cp.async.cg.shared.global [%0], [%1], 16;" \
        :: "r"(dst_u32), "l"(src_ptr))
#define CP_COMMIT() asm volatile("cp.async.commit_group;")
#define CP_WAIT1()  asm volatile("cp.async.wait_group 1;")
#define CP_WAIT0()  asm volatile("cp.async.wait_group 0;")

__device__ __forceinline__ void ldsm_x4(uint32_t& r0, uint32_t& r1,
                                        uint32_t& r2, uint32_t& r3,
                                        uint32_t addr) {
    asm volatile("ldmatrix.sync.aligned.m8n8.x4.shared.b16 {%0,%1,%2,%3}, [%4];"
        : "=r"(r0), "=r"(r1), "=r"(r2), "=r"(r3) : "r"(addr));
}
__device__ __forceinline__ void ldsm_x4_t(uint32_t& r0, uint32_t& r1,
                                          uint32_t& r2, uint32_t& r3,
                                          uint32_t addr) {
    asm volatile("ldmatrix.sync.aligned.m8n8.x4.trans.shared.b16 {%0,%1,%2,%3}, [%4];"
        : "=r"(r0), "=r"(r1), "=r"(r2), "=r"(r3) : "r"(addr));
}

__device__ __forceinline__ void mma_f16(float* c, const uint32_t* a,
                                        const uint32_t* b) {
    asm volatile(
        "mma.sync.aligned.m16n8k16.row.col.f32.f16.f16.f32 "
        "{%0,%1,%2,%3}, {%4,%5,%6,%7}, {%8,%9}, {%0,%1,%2,%3};"
        : "+f"(c[0]), "+f"(c[1]), "+f"(c[2]), "+f"(c[3])
        : "r"(a[0]), "r"(a[1]), "r"(a[2]), "r"(a[3]),
          "r"(b[0]), "r"(b[1]));
}

// ------- fp32 -> fp16 conversion (both weights) + counter zeroing ----------
// Launched FIRST on the stream; zeroing completes before router runs.
__global__ void w2h_kernel(const float* __restrict__ w1,
                           const float* __restrict__ w2,
                           __half* __restrict__ o1,
                           __half* __restrict__ o2, int n4) {
    if (blockIdx.x == 0 && blockIdx.y == 0 && threadIdx.x < N_EXP) {
        g_cnt[threadIdx.x] = 0;
        g_pos[threadIdx.x] = 0;
    }
    int i = blockIdx.x * blockDim.x + threadIdx.x;
    if (i >= n4) return;
    const float* in = blockIdx.y ? w2 : w1;
    __half* out = blockIdx.y ? o2 : o1;
    float4 v = ((const float4*)in)[i];
    __half2* o = (__half2*)(out + (size_t)i * 4);
    o[0] = __floats2half2_rn(v.x, v.y);
    o[1] = __floats2half2_rn(v.z, v.w);
}

// ---------------- router + fused x -> fp16 conversion ------------------------
__global__ void router_kernel(const float* __restrict__ x,
                              const float* __restrict__ Ws,
                              const float* __restrict__ bs) {
    int warp = (blockIdx.x * blockDim.x + threadIdx.x) >> 5;
    int lane = threadIdx.x & 31;
    if (warp >= N_TOK) return;
    const float* xr = x + (size_t)warp * D_MODEL;
    __half* xo = g_xh + (size_t)warp * D_MODEL;
    float acc[N_EXP];
#pragma unroll
    for (int e = 0; e < N_EXP; e++) acc[e] = 0.0f;
    for (int d = lane; d < D_MODEL; d += 32) {
        float xv = xr[d];
        xo[d] = __float2half_rn(xv);
        const float* wr = Ws + d * N_EXP;
#pragma unroll
        for (int e = 0; e < N_EXP; e++) acc[e] += xv * wr[e];
    }
#pragma unroll
    for (int e = 0; e < N_EXP; e++) {
#pragma unroll
        for (int o = 16; o; o >>= 1)
            acc[e] += __shfl_xor_sync(0xffffffffu, acc[e], o);
    }
    if (lane == 0) {
        float l[N_EXP];
        float lmax = -1e30f; int am = 0;
#pragma unroll
        for (int e = 0; e < N_EXP; e++) {
            l[e] = acc[e] + bs[e];
            if (l[e] > lmax) { lmax = l[e]; am = e; }
        }
        float s = 0.0f;
#pragma unroll
        for (int e = 0; e < N_EXP; e++) s += expf(l[e] - lmax);
        g_p[warp] = 1.0f / s;
        g_e[warp] = am;
        atomicAdd(&g_cnt[am], 1);
    }
}

// ---------------- assign (fixed expert segments, no scan) -------------------
__global__ void assign_kernel() {
    int t = blockIdx.x * blockDim.x + threadIdx.x;
    if (t >= N_TOK) return;
    g_rowtok[t] = t;                       // expert-0 segment: identity
    int e = g_e[t];
    if (e != 0) {
        int s = atomicAdd(&g_pos[e], 1);
        int row = e * SEG + s;             // fixed segment base
        g_rowtok[row] = t;
        g_rowidx[t]   = row;
    }
}

// ---------------- fp16 ldmatrix mma GEMM ------------------------------------
// CTA tile 128(m) x 128(n) x 32(k). 256 threads = 8 warps, 4(m) x 2(n),
// warp tile 32x64, mma m16n8k16. A smem [m][k] fp16 pitch 40 halves;
// B smem [k][n] fp16 pitch 136 halves. Both ldmatrix-fed, conflict-free.
// Double-buffered cp.async (fp16 payload). Static smem 37,888 B.
// NSPLIT-way split-K: blockIdx.z = e*NSPLIT+sk; bias added on sk==0 only.
#define KCHUNK 32
#define APITCH_H 40
#define BPITCH_H 136
#define ASZ_H (128 * APITCH_H)        // 5120 halves / stage
#define BSZ_H (KCHUNK * BPITCH_H)     // 4352 halves / stage
#define SMEM_HALVES (2 * ASZ_H + 2 * BSZ_H)   // 18944 halves = 37888 B

template<int KSTRIDE, int KDIM, int NTOT, bool GATHER, bool DO_GELU,
         int NSPLIT, typename OT>
__global__ void __launch_bounds__(256, 2)
gemm_mma(const __half* __restrict__ A, const __half* __restrict__ Bw,
         const float* __restrict__ bias,
         OT* __restrict__ p0, OT* __restrict__ p1,
         OT* __restrict__ p2, OT* __restrict__ p3) {
    int e, sk;
    if (NSPLIT == 1) { e = blockIdx.z; sk = 0; }
    else             { e = blockIdx.z / NSPLIT; sk = blockIdx.z % NSPLIT; }
    const int rows = (e == 0) ? N_TOK : g_cnt[e];
    const int m0   = blockIdx.y * 128;
    if (m0 >= rows) return;
    const int base = e * SEG;
    const int n0   = blockIdx.x * 128;
    const int koff = sk * KDIM;
    OT* optr = (sk == 0) ? p0 : (sk == 1) ? p1 : (sk == 2) ? p2 : p3;

    __shared__ __half sm[SMEM_HALVES];
    const uint32_t smb = smem_u32(sm);

    const int tid  = threadIdx.x;
    const int wid  = tid >> 5;
    const int lane = tid & 31;
    const int wm   = wid & 3;      // m-warp 0..3
    const int wn   = wid >> 2;     // n-warp 0..1
    const int qm   = lane >> 2;    // 0..7
    const int qk   = lane & 3;     // 0..3

    // ---- A cp.async: 128 rows x 32 halves (64B) = 512 x 16B; 2/thread ----
    const int ar = tid >> 2;           // 0..63
    const int ac = tid & 3;            // 0..3 (16B unit in 64B row chunk)
    const __half* asrc[2];
    uint32_t adst[2];
#pragma unroll
    for (int i = 0; i < 2; i++) {
        int r  = ar + i * 64;               // 0..127 tile m row
        int m  = m0 + r;
        int mm = (m < rows) ? m : (rows - 1);
        const __half* rowp;
        if (GATHER) rowp = A + (size_t)g_rowtok[base + mm] * KSTRIDE;
        else        rowp = A + (size_t)(base + mm) * KSTRIDE;
        asrc[i] = rowp + koff + ac * 8;
        adst[i] = (uint32_t)((r * APITCH_H + ac * 8) * 2);
    }
    // ---- B cp.async: 32 k-rows x 128 halves (256B) = 512 x 16B; 2/thread --
    const int bk = tid >> 4;           // 0..15
    const int bc = tid & 15;           // 0..15 (16B unit in 256B row)
    const __half* Bbase =
        Bw + (size_t)e * KSTRIDE * NTOT + (size_t)koff * NTOT + n0 + bc * 8;
    uint32_t bdst[2];
#pragma unroll
    for (int i = 0; i < 2; i++) {
        int kk = bk + i * 16;               // 0..31 tile k row
        bdst[i] = (uint32_t)((kk * BPITCH_H + bc * 8) * 2);
    }

    const uint32_t abuf[2] = { smb, smb + ASZ_H * 2 };
    const uint32_t bbuf[2] = { smb + 2 * ASZ_H * 2,
                               smb + (2 * ASZ_H + BSZ_H) * 2 };

    auto load_chunk = [&](int buf, int k0) {
#pragma unroll
        for (int i = 0; i < 2; i++)
            CP_ASYNC16(abuf[buf] + adst[i], asrc[i] + k0);
#pragma unroll
        for (int i = 0; i < 2; i++)
            CP_ASYNC16(bbuf[buf] + bdst[i],
                       Bbase + (size_t)(k0 + bk + i * 16) * NTOT);
        CP_COMMIT();
    };

    // ---- ldmatrix per-lane address components ----
    const uint32_t a_lm =
        (uint32_t)(((wm * 32 + (lane & 15)) * APITCH_H + (lane >> 4) * 8) * 2);
    const uint32_t b_lm =
        (uint32_t)(((lane & 15) * BPITCH_H + wn * 64 + (lane >> 4) * 8) * 2);

    float acc[2][8][4];
#pragma unroll
    for (int tm = 0; tm < 2; tm++)
#pragma unroll
        for (int tn = 0; tn < 8; tn++)
#pragma unroll
            for (int j = 0; j < 4; j++) acc[tm][tn][j] = 0.0f;

    const int NC = KDIM / KCHUNK;
    load_chunk(0, 0);

    for (int ch = 0; ch < NC; ch++) {
        int buf = ch & 1;
        if (ch + 1 < NC) { load_chunk((ch + 1) & 1, (ch + 1) * KCHUNK); CP_WAIT1(); }
        else             { CP_WAIT0(); }
        __syncthreads();

        const uint32_t a0 = abuf[buf] + a_lm;
        const uint32_t b0 = bbuf[buf] + b_lm;
#pragma unroll
        for (int k16 = 0; k16 < KCHUNK / 16; k16++) {
            uint32_t afr[2][4];
#pragma unroll
            for (int tm = 0; tm < 2; tm++)
                ldsm_x4(afr[tm][0], afr[tm][1], afr[tm][2], afr[tm][3],
                        a0 + (uint32_t)((tm * 16 * APITCH_H + k16 * 16) * 2));
            uint32_t bfr[8][2];
#pragma unroll
            for (int j = 0; j < 4; j++) {
                uint32_t r0, r1, r2, r3;
                ldsm_x4_t(r0, r1, r2, r3,
                          b0 + (uint32_t)((k16 * 16 * BPITCH_H + j * 16) * 2));
                bfr[2 * j + 0][0] = r0; bfr[2 * j + 0][1] = r1;
                bfr[2 * j + 1][0] = r2; bfr[2 * j + 1][1] = r3;
            }
#pragma unroll
            for (int tm = 0; tm < 2; tm++)
#pragma unroll
                for (int tn = 0; tn < 8; tn++)
                    mma_f16(acc[tm][tn], afr[tm], bfr[tn]);
        }
        __syncthreads();
    }

    // ---- epilogue: bias (+ gelu) on sk==0 only; direct global stores ----
    const bool add_bias = (sk == 0);
    const float* bp_e = bias + (size_t)e * NTOT + n0 + wn * 64;
#pragma unroll
    for (int tm = 0; tm < 2; tm++) {
        int r0 = m0 + wm * 32 + tm * 16 + qm;
#pragma unroll
        for (int half = 0; half < 2; half++) {
            int r = r0 + half * 8;
            if (r >= rows) continue;
            OT* orow = optr + (size_t)(base + r) * NTOT + n0 + wn * 64;
#pragma unroll
            for (int tn = 0; tn < 8; tn++) {
                int c = tn * 8 + qk * 2;
                float v0 = acc[tm][tn][half * 2 + 0];
                float v1 = acc[tm][tn][half * 2 + 1];
                if (add_bias) {
                    v0 += __ldg(bp_e + c + 0);
                    v1 += __ldg(bp_e + c + 1);
                }
                if (DO_GELU) {
                    v0 = 0.5f * v0 * (1.0f + erff(v0 * 0.70710678118654752f));
                    v1 = 0.5f * v1 * (1.0f + erff(v1 * 0.70710678118654752f));
                }
                if (sizeof(OT) == 2) {
                    *(__half2*)((__half*)orow + c) = __floats2half2_rn(v0, v1);
                } else {
                    *(float2*)((float*)orow + c) = make_float2(v0, v1);
                }
            }
        }
    }
}

// ---------------- combine (sums 4 split-K partials) --------------------------
__global__ void combine_kernel(float* __restrict__ out) {
    int idx = blockIdx.x * blockDim.x + threadIdx.x;
    if (idx >= N_TOK * D_MODEL) return;
    int t = idx / D_MODEL;
    float y0 = g_y[idx] + g_y2[idx] + g_y3[idx] + g_y4[idx];
    int e = g_e[t];
    float r;
    if (e == 0) {
        r = y0;
    } else {
        float p  = g_p[t];
        size_t ri = (size_t)g_rowidx[t] * D_MODEL + (idx - t * D_MODEL);
        float ye = g_y[ri] + g_y2[ri] + g_y3[ri] + g_y4[ri];
        r = p * ye + (1.0f - p) * y0;
    }
    out[idx] = r;
}

// ---------------- launch ----------------------------------------------------
extern "C" void kernel_launch(void* const* d_in, const int* in_sizes, int n_in,
                              void* d_out, int out_size) {
    const float* x  = (const float*)d_in[0];
    const float* Ws = (const float*)d_in[1];
    const float* bs = (const float*)d_in[2];
    const float* W1 = (const float*)d_in[3];
    const float* b1 = (const float*)d_in[4];
    const float* W2 = (const float*)d_in[5];
    const float* b2 = (const float*)d_in[6];
    float* out = (float*)d_out;

    // CRITICAL: __device__ symbols must be resolved to DEVICE addresses here.
    __half* xh;  cudaGetSymbolAddress((void**)&xh,  g_xh);
    __half* w1h; cudaGetSymbolAddress((void**)&w1h, g_w1h);
    __half* w2h; cudaGetSymbolAddress((void**)&w2h, g_w2h);
    __half* hh;  cudaGetSymbolAddress((void**)&hh,  g_hh);
    float *ybuf, *ybuf2, *ybuf3, *ybuf4;
    cudaGetSymbolAddress((void**)&ybuf,  g_y);
    cudaGetSymbolAddress((void**)&ybuf2, g_y2);
    cudaGetSymbolAddress((void**)&ybuf3, g_y3);
    cudaGetSymbolAddress((void**)&ybuf4, g_y4);

    // weight fp16 conversion + counter zeroing (FIRST: zeroing precedes router)
    {
        int n4 = N_EXP * D_MODEL * D_FF / 4;
        w2h_kernel<<<dim3((n4 + 255) / 256, 2), 256>>>(W1, W2, w1h, w2h, n4);
    }
    router_kernel<<<N_TOK / 8, 256>>>(x, Ws, bs);   // also writes g_xh
    assign_kernel<<<N_TOK / 256, 256>>>();

    // GEMM1: h = gelu(x @ W1 + b1); gathered fp16 x rows, fp16 W1, fp16 out
    gemm_mma<D_MODEL, D_MODEL, D_FF, true, true, 1, __half>
        <<<dim3(D_FF / 128, N_TOK / 128, N_EXP), 256>>>(
            xh, w1h, b1, hh, hh, hh, hh);
    // GEMM2: y = h @ W2 + b2; split-K=4 -> partials in g_y..g_y4
    gemm_mma<D_FF, D_FF / 4, D_MODEL, false, false, 4, float>
        <<<dim3(D_MODEL / 128, N_TOK / 128, N_EXP * 4), 256>>>(
            hh, w2h, b2, ybuf, ybuf2, ybuf3, ybuf4);

    combine_kernel<<<(N_TOK * D_MODEL + 255) / 256, 256>>>(out);
}

// round 17
// speedup vs baseline: 2.1457x; 1.0452x over previous
#include <cuda_runtime.h>
#include <cuda_fp16.h>
#include <cstdint>
#include <math.h>

#define D_MODEL 768
#define D_FF    3072
#define N_EXP   9
#define N_TOK   2048
#define SEG     2048                  // fixed rows per expert segment
#define MAXR    (SEG * N_EXP)         // 18432 rows

// ---------------- scratch (device globals: no allocation allowed) ----------
__device__ __half g_xh[N_TOK * D_MODEL];          // x in fp16
__device__ __half g_w1h[N_EXP * D_MODEL * D_FF];  // W1 in fp16
__device__ __half g_w2h[N_EXP * D_FF * D_MODEL];  // W2 in fp16
__device__ __half g_hh[(size_t)MAXR * D_FF];      // hidden activations fp16
__device__ float  g_y[(size_t)MAXR * D_MODEL];    // split-K partial 0 (+bias)
__device__ float  g_y2[(size_t)MAXR * D_MODEL];   // split-K partial 1
__device__ float  g_y3[(size_t)MAXR * D_MODEL];   // split-K partial 2
__device__ float  g_y4[(size_t)MAXR * D_MODEL];   // split-K partial 3
__device__ float  g_p[N_TOK];
__device__ int    g_e[N_TOK];
__device__ int    g_cnt[N_EXP];
__device__ int    g_pos[N_EXP];
__device__ int    g_rowtok[MAXR];
__device__ int    g_rowidx[N_TOK];

// ---------------- PTX helpers (sm_75+/80+, compute_103-safe) ---------------
__device__ __forceinline__ uint32_t smem_u32(const void* p) {
    uint32_t a;
    asm("{ .reg .u64 t; cvta.to.shared.u64 t, %1; cvt.u32.u64 %0, t; }"
        : "=r"(a) : "l"(p));
    return a;
}
#define CP_ASYNC16(dst_u32, src_ptr) \
    asm volatile("cp.async.cg.shared.global [%0], [%1], 16;" \
        :: "r"(dst_u32), "l"(src_ptr))
#define CP_COMMIT() asm volatile("cp.async.commit_group;")
#define CP_WAIT1()  asm volatile("cp.async.wait_group 1;")

__device__ __forceinline__ void ldsm_x4(uint32_t& r0, uint32_t& r1,
                                        uint32_t& r2, uint32_t& r3,
                                        uint32_t addr) {
    asm volatile("ldmatrix.sync.aligned.m8n8.x4.shared.b16 {%0,%1,%2,%3}, [%4];"
        : "=r"(r0), "=r"(r1), "=r"(r2), "=r"(r3) : "r"(addr));
}
__device__ __forceinline__ void ldsm_x4_t(uint32_t& r0, uint32_t& r1,
                                          uint32_t& r2, uint32_t& r3,
                                          uint32_t addr) {
    asm volatile("ldmatrix.sync.aligned.m8n8.x4.trans.shared.b16 {%0,%1,%2,%3}, [%4];"
        : "=r"(r0), "=r"(r1), "=r"(r2), "=r"(r3) : "r"(addr));
}

__device__ __forceinline__ void mma_f16(float* c, const uint32_t* a,
                                        const uint32_t* b) {
    asm volatile(
        "mma.sync.aligned.m16n8k16.row.col.f32.f16.f16.f32 "
        "{%0,%1,%2,%3}, {%4,%5,%6,%7}, {%8,%9}, {%0,%1,%2,%3};"
        : "+f"(c[0]), "+f"(c[1]), "+f"(c[2]), "+f"(c[3])
        : "r"(a[0]), "r"(a[1]), "r"(a[2]), "r"(a[3]),
          "r"(b[0]), "r"(b[1]));
}

// ---------------- fp32 -> fp16 conversion (single tensor) -------------------
__global__ void f2h_kernel(const float* __restrict__ in,
                           __half* __restrict__ out, int n4) {
    int i = blockIdx.x * blockDim.x + threadIdx.x;
    if (i >= n4) return;
    float4 v = ((const float4*)in)[i];
    __half2* o = (__half2*)(out + (size_t)i * 4);
    o[0] = __floats2half2_rn(v.x, v.y);
    o[1] = __floats2half2_rn(v.z, v.w);
}

// ---------------- tiny bookkeeping kernels ---------------------------------
__global__ void zero_kernel() {
    int i = threadIdx.x;
    if (i < N_EXP) { g_cnt[i] = 0; g_pos[i] = 0; }
}

// router + fused x -> fp16 conversion
__global__ void router_kernel(const float* __restrict__ x,
                              const float* __restrict__ Ws,
                              const float* __restrict__ bs) {
    int warp = (blockIdx.x * blockDim.x + threadIdx.x) >> 5;
    int lane = threadIdx.x & 31;
    if (warp >= N_TOK) return;
    const float* xr = x + (size_t)warp * D_MODEL;
    __half* xo = g_xh + (size_t)warp * D_MODEL;
    float acc[N_EXP];
#pragma unroll
    for (int e = 0; e < N_EXP; e++) acc[e] = 0.0f;
    for (int d = lane; d < D_MODEL; d += 32) {
        float xv = xr[d];
        xo[d] = __float2half_rn(xv);
        const float* wr = Ws + d * N_EXP;
#pragma unroll
        for (int e = 0; e < N_EXP; e++) acc[e] += xv * wr[e];
    }
#pragma unroll
    for (int e = 0; e < N_EXP; e++) {
#pragma unroll
        for (int o = 16; o; o >>= 1)
            acc[e] += __shfl_xor_sync(0xffffffffu, acc[e], o);
    }
    if (lane == 0) {
        float l[N_EXP];
        float lmax = -1e30f; int am = 0;
#pragma unroll
        for (int e = 0; e < N_EXP; e++) {
            l[e] = acc[e] + bs[e];
            if (l[e] > lmax) { lmax = l[e]; am = e; }
        }
        float s = 0.0f;
#pragma unroll
        for (int e = 0; e < N_EXP; e++) s += expf(l[e] - lmax);
        g_p[warp] = 1.0f / s;
        g_e[warp] = am;
        atomicAdd(&g_cnt[am], 1);
    }
}

// ---------------- assign (fixed expert segments, no scan) -------------------
__global__ void assign_kernel() {
    int t = blockIdx.x * blockDim.x + threadIdx.x;
    if (t >= N_TOK) return;
    g_rowtok[t] = t;                       // expert-0 segment: identity
    int e = g_e[t];
    if (e != 0) {
        int s = atomicAdd(&g_pos[e], 1);
        int row = e * SEG + s;             // fixed segment base
        g_rowtok[row] = t;
        g_rowidx[t]   = row;
    }
}

// ---------------- fp16 ldmatrix mma GEMM ------------------------------------
// CTA tile 128(m) x 128(n) x 32(k). 256 threads = 8 warps, 4(m) x 2(n),
// warp tile 32x64, mma m16n8k16. A smem [m][k] fp16 pitch 40 halves;
// B smem [k][n] fp16 pitch 136 halves. Both ldmatrix-fed, conflict-free.
// 3-stage cp.async ring, ONE barrier per chunk. Dyn smem 56,832 B (opt-in).
// NSPLIT-way split-K: blockIdx.z = e*NSPLIT+sk; bias added on sk==0 only.
#define KCHUNK 32
#define APITCH_H 40
#define BPITCH_H 136
#define ASZ_H (128 * APITCH_H)        // 5120 halves / stage
#define BSZ_H (KCHUNK * BPITCH_H)     // 4352 halves / stage
#define STG_H (ASZ_H + BSZ_H)         // 9472 halves / stage
#define SMEM_BYTES (3 * STG_H * 2)    // 56,832 B

template<int KSTRIDE, int KDIM, int NTOT, bool GATHER, bool DO_GELU,
         int NSPLIT, typename OT>
__global__ void __launch_bounds__(256, 2)
gemm_mma(const __half* __restrict__ A, const __half* __restrict__ Bw,
         const float* __restrict__ bias,
         OT* __restrict__ p0, OT* __restrict__ p1,
         OT* __restrict__ p2, OT* __restrict__ p3) {
    int e, sk;
    if (NSPLIT == 1) { e = blockIdx.z; sk = 0; }
    else             { e = blockIdx.z / NSPLIT; sk = blockIdx.z % NSPLIT; }
    const int rows = (e == 0) ? N_TOK : g_cnt[e];
    const int m0   = blockIdx.y * 128;
    if (m0 >= rows) return;
    const int base = e * SEG;
    const int n0   = blockIdx.x * 128;
    const int koff = sk * KDIM;
    OT* optr = (sk == 0) ? p0 : (sk == 1) ? p1 : (sk == 2) ? p2 : p3;

    extern __shared__ __half smx[];
    const uint32_t smb = smem_u32(smx);
    uint32_t abuf[3], bbuf[3];
#pragma unroll
    for (int s = 0; s < 3; s++) {
        abuf[s] = smb + (uint32_t)(s * STG_H) * 2;
        bbuf[s] = abuf[s] + ASZ_H * 2;
    }

    const int tid  = threadIdx.x;
    const int wid  = tid >> 5;
    const int lane = tid & 31;
    const int wm   = wid & 3;      // m-warp 0..3
    const int wn   = wid >> 2;     // n-warp 0..1
    const int qm   = lane >> 2;    // 0..7
    const int qk   = lane & 3;     // 0..3

    // ---- A cp.async: 128 rows x 32 halves (64B) = 512 x 16B; 2/thread ----
    const int ar = tid >> 2;           // 0..63
    const int ac = tid & 3;            // 0..3 (16B unit in 64B row chunk)
    const __half* asrc[2];
    uint32_t adst[2];
#pragma unroll
    for (int i = 0; i < 2; i++) {
        int r  = ar + i * 64;               // 0..127 tile m row
        int m  = m0 + r;
        int mm = (m < rows) ? m : (rows - 1);
        const __half* rowp;
        if (GATHER) rowp = A + (size_t)g_rowtok[base + mm] * KSTRIDE;
        else        rowp = A + (size_t)(base + mm) * KSTRIDE;
        asrc[i] = rowp + koff + ac * 8;
        adst[i] = (uint32_t)((r * APITCH_H + ac * 8) * 2);
    }
    // ---- B cp.async: 32 k-rows x 128 halves (256B) = 512 x 16B; 2/thread --
    const int bk = tid >> 4;           // 0..15
    const int bc = tid & 15;           // 0..15 (16B unit in 256B row)
    const __half* Bbase =
        Bw + (size_t)e * KSTRIDE * NTOT + (size_t)koff * NTOT + n0 + bc * 8;
    uint32_t bdst[2];
#pragma unroll
    for (int i = 0; i < 2; i++) {
        int kk = bk + i * 16;               // 0..31 tile k row
        bdst[i] = (uint32_t)((kk * BPITCH_H + bc * 8) * 2);
    }

    auto load_chunk = [&](int buf, int k0) {
#pragma unroll
        for (int i = 0; i < 2; i++)
            CP_ASYNC16(abuf[buf] + adst[i], asrc[i] + k0);
#pragma unroll
        for (int i = 0; i < 2; i++)
            CP_ASYNC16(bbuf[buf] + bdst[i],
                       Bbase + (size_t)(k0 + bk + i * 16) * NTOT);
        CP_COMMIT();
    };

    // ---- ldmatrix per-lane address components ----
    const uint32_t a_lm =
        (uint32_t)(((wm * 32 + (lane & 15)) * APITCH_H + (lane >> 4) * 8) * 2);
    const uint32_t b_lm =
        (uint32_t)(((lane & 15) * BPITCH_H + wn * 64 + (lane >> 4) * 8) * 2);

    float acc[2][8][4];
#pragma unroll
    for (int tm = 0; tm < 2; tm++)
#pragma unroll
        for (int tn = 0; tn < 8; tn++)
#pragma unroll
            for (int j = 0; j < 4; j++) acc[tm][tn][j] = 0.0f;

    const int NC = KDIM / KCHUNK;       // >= 24 for both GEMMs
    load_chunk(0, 0);
    load_chunk(1, KCHUNK);
    CP_WAIT1();                         // chunk 0 arrived
    __syncthreads();

    int bufc = 0, bufn = 2;
    for (int ch = 0; ch < NC; ch++) {
        if (ch + 2 < NC) load_chunk(bufn, (ch + 2) * KCHUNK);
        else             CP_COMMIT();   // empty group keeps counting uniform

        const uint32_t a0 = abuf[bufc] + a_lm;
        const uint32_t b0 = bbuf[bufc] + b_lm;
#pragma unroll
        for (int k16 = 0; k16 < KCHUNK / 16; k16++) {
            uint32_t afr[2][4];
#pragma unroll
            for (int tm = 0; tm < 2; tm++)
                ldsm_x4(afr[tm][0], afr[tm][1], afr[tm][2], afr[tm][3],
                        a0 + (uint32_t)((tm * 16 * APITCH_H + k16 * 16) * 2));
            uint32_t bfr[8][2];
#pragma unroll
            for (int j = 0; j < 4; j++) {
                uint32_t r0, r1, r2, r3;
                ldsm_x4_t(r0, r1, r2, r3,
                          b0 + (uint32_t)((k16 * 16 * BPITCH_H + j * 16) * 2));
                bfr[2 * j + 0][0] = r0; bfr[2 * j + 0][1] = r1;
                bfr[2 * j + 1][0] = r2; bfr[2 * j + 1][1] = r3;
            }
#pragma unroll
            for (int tm = 0; tm < 2; tm++)
#pragma unroll
                for (int tn = 0; tn < 8; tn++)
                    mma_f16(acc[tm][tn], afr[tm], bfr[tn]);
        }

        CP_WAIT1();                     // next chunk arrived
        __syncthreads();                // reads of bufc done; bufn reusable
        bufc = (bufc == 2) ? 0 : bufc + 1;
        bufn = (bufn == 2) ? 0 : bufn + 1;
    }

    // ---- epilogue: bias (+ gelu) on sk==0 only; direct global stores ----
    const bool add_bias = (sk == 0);
    const float* bp_e = bias + (size_t)e * NTOT + n0 + wn * 64;
#pragma unroll
    for (int tm = 0; tm < 2; tm++) {
        int r0 = m0 + wm * 32 + tm * 16 + qm;
#pragma unroll
        for (int half = 0; half < 2; half++) {
            int r = r0 + half * 8;
            if (r >= rows) continue;
            OT* orow = optr + (size_t)(base + r) * NTOT + n0 + wn * 64;
#pragma unroll
            for (int tn = 0; tn < 8; tn++) {
                int c = tn * 8 + qk * 2;
                float v0 = acc[tm][tn][half * 2 + 0];
                float v1 = acc[tm][tn][half * 2 + 1];
                if (add_bias) {
                    v0 += __ldg(bp_e + c + 0);
                    v1 += __ldg(bp_e + c + 1);
                }
                if (DO_GELU) {
                    v0 = 0.5f * v0 * (1.0f + erff(v0 * 0.70710678118654752f));
                    v1 = 0.5f * v1 * (1.0f + erff(v1 * 0.70710678118654752f));
                }
                if (sizeof(OT) == 2) {
                    *(__half2*)((__half*)orow + c) = __floats2half2_rn(v0, v1);
                } else {
                    *(float2*)((float*)orow + c) = make_float2(v0, v1);
                }
            }
        }
    }
}

// ---------------- combine (sums 4 split-K partials) --------------------------
__global__ void combine_kernel(float* __restrict__ out) {
    int idx = blockIdx.x * blockDim.x + threadIdx.x;
    if (idx >= N_TOK * D_MODEL) return;
    int t = idx / D_MODEL;
    float y0 = g_y[idx] + g_y2[idx] + g_y3[idx] + g_y4[idx];
    int e = g_e[t];
    float r;
    if (e == 0) {
        r = y0;
    } else {
        float p  = g_p[t];
        size_t ri = (size_t)g_rowidx[t] * D_MODEL + (idx - t * D_MODEL);
        float ye = g_y[ri] + g_y2[ri] + g_y3[ri] + g_y4[ri];
        r = p * ye + (1.0f - p) * y0;
    }
    out[idx] = r;
}

// ---------------- launch ----------------------------------------------------
extern "C" void kernel_launch(void* const* d_in, const int* in_sizes, int n_in,
                              void* d_out, int out_size) {
    const float* x  = (const float*)d_in[0];
    const float* Ws = (const float*)d_in[1];
    const float* bs = (const float*)d_in[2];
    const float* W1 = (const float*)d_in[3];
    const float* b1 = (const float*)d_in[4];
    const float* W2 = (const float*)d_in[5];
    const float* b2 = (const float*)d_in[6];
    float* out = (float*)d_out;

    // CRITICAL: __device__ symbols must be resolved to DEVICE addresses here.
    __half* xh;  cudaGetSymbolAddress((void**)&xh,  g_xh);
    __half* w1h; cudaGetSymbolAddress((void**)&w1h, g_w1h);
    __half* w2h; cudaGetSymbolAddress((void**)&w2h, g_w2h);
    __half* hh;  cudaGetSymbolAddress((void**)&hh,  g_hh);
    float *ybuf, *ybuf2, *ybuf3, *ybuf4;
    cudaGetSymbolAddress((void**)&ybuf,  g_y);
    cudaGetSymbolAddress((void**)&ybuf2, g_y2);
    cudaGetSymbolAddress((void**)&ybuf3, g_y3);
    cudaGetSymbolAddress((void**)&ybuf4, g_y4);

    // one-time: side streams + events (host-side setup; no device allocation)
    static cudaStream_t s1 = nullptr, s2 = nullptr;
    static cudaEvent_t evRoot = nullptr, evW2 = nullptr, evRt = nullptr;
    static bool attr_done = false;
    if (!s1) {
        cudaStreamCreateWithFlags(&s1, cudaStreamNonBlocking);
        cudaStreamCreateWithFlags(&s2, cudaStreamNonBlocking);
        cudaEventCreateWithFlags(&evRoot, cudaEventDisableTiming);
        cudaEventCreateWithFlags(&evW2,   cudaEventDisableTiming);
        cudaEventCreateWithFlags(&evRt,   cudaEventDisableTiming);
    }
    if (!attr_done) {
        cudaFuncSetAttribute(
            (const void*)gemm_mma<D_MODEL, D_MODEL, D_FF, true, true, 1, __half>,
            cudaFuncAttributeMaxDynamicSharedMemorySize, SMEM_BYTES);
        cudaFuncSetAttribute(
            (const void*)gemm_mma<D_FF, D_FF / 4, D_MODEL, false, false, 4, float>,
            cudaFuncAttributeMaxDynamicSharedMemorySize, SMEM_BYTES);
        attr_done = true;
    }

    const int n4 = N_EXP * D_MODEL * D_FF / 4;

    // fork side streams off the capture (legacy) stream
    cudaEventRecord(evRoot, 0);
    cudaStreamWaitEvent(s1, evRoot, 0);
    cudaStreamWaitEvent(s2, evRoot, 0);

    // s1: W2 -> fp16 (only needed by GEMM2)
    f2h_kernel<<<(n4 + 255) / 256, 256, 0, s1>>>(W2, w2h, n4);
    cudaEventRecord(evW2, s1);

    // s2: routing chain (zero -> router(+x->fp16) -> assign)
    zero_kernel<<<1, 32, 0, s2>>>();
    router_kernel<<<N_TOK / 8, 256, 0, s2>>>(x, Ws, bs);
    assign_kernel<<<N_TOK / 256, 256, 0, s2>>>();
    cudaEventRecord(evRt, s2);

    // main stream: W1 -> fp16 (needed by GEMM1), concurrent with s1/s2
    f2h_kernel<<<(n4 + 255) / 256, 256>>>(W1, w1h, n4);

    // join routing, then GEMM1
    cudaStreamWaitEvent(0, evRt, 0);
    gemm_mma<D_MODEL, D_MODEL, D_FF, true, true, 1, __half>
        <<<dim3(D_FF / 128, N_TOK / 128, N_EXP), 256, SMEM_BYTES>>>(
            xh, w1h, b1, hh, hh, hh, hh);

    // join W2 conversion, then GEMM2 (split-K=4)
    cudaStreamWaitEvent(0, evW2, 0);
    gemm_mma<D_FF, D_FF / 4, D_MODEL, false, false, 4, float>
        <<<dim3(D_MODEL / 128, N_TOK / 128, N_EXP * 4), 256, SMEM_BYTES>>>(
            hh, w2h, b2, ybuf, ybuf2, ybuf3, ybuf4);

    combine_kernel<<<(N_TOK * D_MODEL + 255) / 256, 256>>>(out);
}